// round 4
// baseline (speedup 1.0000x reference)
#include <cuda_runtime.h>
#include <cuda_bf16.h>
#include <cstdint>

#define BB 8
#define TT 128
#define DD 512
#define MM (BB*TT)          // 1024 tokens
#define NWT 6
#define NN (NWT*DD)         // 3072 total output cols
#define KP 1536             // split-K': [hi|hi|lo] x [hi|lo|hi]
#define KC 64               // K-chunk (64 bf16 = 128B = swizzle-atom row)
#define NCH (KP/KC)         // 24 chunks
#define MT 128
#define NT 128
#define GSMEM (64*1024)

typedef unsigned long long ull;

__device__ float g_proj[NWT * MM * DD];          // 12 MB fp32 projections
__device__ __nv_bfloat16 gA[(size_t)MM * KP];    // 3 MB packed A'
__device__ __nv_bfloat16 gB[(size_t)NN * KP];    // 9 MB packed B'

struct WPtrs { const float* W[NWT]; const float* b[NWT]; };

// ---------------------------------------------------------------------------
// helpers (family-agnostic PTX: cp.async / ldmatrix / mma.sync / ex2 / f32x2)
// ---------------------------------------------------------------------------
__device__ __forceinline__ uint32_t smem_u32(const void* p) {
    uint32_t a;
    asm("{ .reg .u64 t; cvta.to.shared.u64 t, %1; cvt.u32.u64 %0, t; }" : "=r"(a) : "l"(p));
    return a;
}
__device__ __forceinline__ void cp16(uint32_t saddr, const void* g) {
    asm volatile("cp.async.cg.shared.global [%0], [%1], 16;" :: "r"(saddr), "l"(g));
}
__device__ __forceinline__ void cp_commit() { asm volatile("cp.async.commit_group;" ::: "memory"); }
__device__ __forceinline__ void cp_wait1()  { asm volatile("cp.async.wait_group 1;" ::: "memory"); }
__device__ __forceinline__ void cp_wait0()  { asm volatile("cp.async.wait_group 0;" ::: "memory"); }
__device__ __forceinline__ void ldsm4(uint32_t* d, uint32_t a) {
    asm volatile("ldmatrix.sync.aligned.m8n8.x4.shared.b16 {%0,%1,%2,%3}, [%4];"
        : "=r"(d[0]), "=r"(d[1]), "=r"(d[2]), "=r"(d[3]) : "r"(a));
}
__device__ __forceinline__ void mma16816(float* c, const uint32_t* a, uint32_t b0, uint32_t b1) {
    asm volatile(
        "mma.sync.aligned.m16n8k16.row.col.f32.bf16.bf16.f32 "
        "{%0,%1,%2,%3}, {%4,%5,%6,%7}, {%8,%9}, {%0,%1,%2,%3};"
        : "+f"(c[0]), "+f"(c[1]), "+f"(c[2]), "+f"(c[3])
        : "r"(a[0]), "r"(a[1]), "r"(a[2]), "r"(a[3]), "r"(b0), "r"(b1));
}
__device__ __forceinline__ float ex2f(float x) { float y; asm("ex2.approx.f32 %0, %1;" : "=f"(y) : "f"(x)); return y; }

// packed f32x2 ops (sm_100+ family, not arch-suffix gated)
__device__ __forceinline__ ull f2fma(ull a, ull b, ull c) {
    ull r; asm("fma.rn.f32x2 %0, %1, %2, %3;" : "=l"(r) : "l"(a), "l"(b), "l"(c)); return r;
}
__device__ __forceinline__ ull f2add(ull a, ull b) {
    ull r; asm("add.rn.f32x2 %0, %1, %2;" : "=l"(r) : "l"(a), "l"(b)); return r;
}
__device__ __forceinline__ ull pack2(float lo, float hi) {
    ull r; asm("mov.b64 %0, {%1, %2};" : "=l"(r) : "f"(lo), "f"(hi)); return r;
}
__device__ __forceinline__ float lo32(ull v) {
    float f; asm("{ .reg .f32 h; mov.b64 {%0, h}, %1; }" : "=f"(f) : "l"(v)); return f;
}
__device__ __forceinline__ float hi32(ull v) {
    float f; asm("{ .reg .f32 l; mov.b64 {l, %0}, %1; }" : "=f"(f) : "l"(v)); return f;
}

#define SW128(o) ((o) ^ (((o) >> 3) & 0x70))

// ---------------------------------------------------------------------------
// fp32 -> bf16 hi/lo split & pack
// ---------------------------------------------------------------------------
__global__ __launch_bounds__(256) void conv_x(const float* __restrict__ x) {
    int idx = blockIdx.x * 256 + threadIdx.x;        // < 131072
    int m = idx >> 7;
    int k4 = (idx & 127) << 2;
    float4 v = *(const float4*)&x[(size_t)m * DD + k4];
    __nv_bfloat16 h[4], l[4];
    float vv[4] = {v.x, v.y, v.z, v.w};
    #pragma unroll
    for (int i = 0; i < 4; i++) {
        h[i] = __float2bfloat16_rn(vv[i]);
        l[i] = __float2bfloat16_rn(vv[i] - __bfloat162float(h[i]));
    }
    __nv_bfloat162* p0 = (__nv_bfloat162*)&gA[(size_t)m * KP + k4];
    p0[0] = {h[0], h[1]}; p0[1] = {h[2], h[3]};
    __nv_bfloat162* p1 = (__nv_bfloat162*)&gA[(size_t)m * KP + 512 + k4];
    p1[0] = {h[0], h[1]}; p1[1] = {h[2], h[3]};
    __nv_bfloat162* p2 = (__nv_bfloat162*)&gA[(size_t)m * KP + 1024 + k4];
    p2[0] = {l[0], l[1]}; p2[1] = {l[2], l[3]};
}

__global__ __launch_bounds__(256) void conv_w(WPtrs p) {
    int idx = blockIdx.x * 256 + threadIdx.x;        // < 393216
    int flat = idx << 2;
    int w = flat >> 18;
    int o = (flat >> 9) & 511;
    int k4 = flat & 511;
    float4 v = *(const float4*)&p.W[w][(size_t)o * DD + k4];
    __nv_bfloat16 h[4], l[4];
    float vv[4] = {v.x, v.y, v.z, v.w};
    #pragma unroll
    for (int i = 0; i < 4; i++) {
        h[i] = __float2bfloat16_rn(vv[i]);
        l[i] = __float2bfloat16_rn(vv[i] - __bfloat162float(h[i]));
    }
    size_t row = (size_t)(w * DD + o) * KP;
    __nv_bfloat162* p0 = (__nv_bfloat162*)&gB[row + k4];
    p0[0] = {h[0], h[1]}; p0[1] = {h[2], h[3]};
    __nv_bfloat162* p1 = (__nv_bfloat162*)&gB[row + 512 + k4];
    p1[0] = {l[0], l[1]}; p1[1] = {l[2], l[3]};
    __nv_bfloat162* p2 = (__nv_bfloat162*)&gB[row + 1024 + k4];
    p2[0] = {h[0], h[1]}; p2[1] = {h[2], h[3]};
}

// ---------------------------------------------------------------------------
// mma.sync GEMM (unchanged from R3)
// ---------------------------------------------------------------------------
__device__ __forceinline__ void load_chunk(int tid, int m0, int ng, int c,
                                           uint32_t sAb, uint32_t sBb) {
    const int kb = c * KC;
    #pragma unroll
    for (int t = 0; t < 4; t++) {
        int idx = tid + t * 256;
        int row = idx >> 3, c16 = idx & 7;
        const char* ga = (const char*)gA + ((size_t)(m0 + row) * KP + kb) * 2 + c16 * 16;
        cp16(sAb + SW128(row * 128 + c16 * 16), ga);
    }
    #pragma unroll
    for (int t = 0; t < 4; t++) {
        int idx = tid + t * 256;
        int row = idx >> 3, c16 = idx & 7;
        const char* gb = (const char*)gB + ((size_t)(ng + row) * KP + kb) * 2 + c16 * 16;
        cp16(sBb + SW128(row * 128 + c16 * 16), gb);
    }
    cp_commit();
}

__global__ __launch_bounds__(256, 2) void gemm_mma(WPtrs p) {
    extern __shared__ __align__(1024) char dsm[];
    const uint32_t sbase = smem_u32(dsm);
    const uint32_t sA[2] = {sbase,            sbase + 16384u};
    const uint32_t sB[2] = {sbase + 32768u,   sbase + 49152u};

    const int tid  = threadIdx.x;
    const int wid  = tid >> 5, lane = tid & 31;
    const int wm   = wid & 3;
    const int wn   = wid >> 2;
    const int m0 = blockIdx.x * MT;
    const int ng = blockIdx.y * NT;

    float acc[2][8][4];
    #pragma unroll
    for (int i = 0; i < 2; i++)
        #pragma unroll
        for (int j = 0; j < 8; j++)
            #pragma unroll
            for (int q = 0; q < 4; q++) acc[i][j][q] = 0.f;

    load_chunk(tid, m0, ng, 0, sA[0], sB[0]);
    load_chunk(tid, m0, ng, 1, sA[1], sB[1]);

    const int a_row  = wm * 32 + (lane & 15);
    const int a_koff = ((lane >> 4) << 3) * 2;
    const int b_row  = wn * 64 + (lane & 7) + ((lane >> 4) << 3);
    const int b_koff = (((lane >> 3) & 1) << 3) * 2;

    for (int ch = 0; ch < NCH; ch++) {
        const int buf = ch & 1;
        if (ch < NCH - 1) cp_wait1(); else cp_wait0();
        __syncthreads();

        #pragma unroll
        for (int ks = 0; ks < 4; ks++) {
            const int kb = ks * 32;
            uint32_t a[2][4];
            #pragma unroll
            for (int mt = 0; mt < 2; mt++)
                ldsm4(a[mt], sA[buf] + SW128((a_row + mt * 16) * 128 + kb + a_koff));
            uint32_t b[4][4];
            #pragma unroll
            for (int nt = 0; nt < 4; nt++)
                ldsm4(b[nt], sB[buf] + SW128((b_row + nt * 16) * 128 + kb + b_koff));
            #pragma unroll
            for (int mt = 0; mt < 2; mt++)
                #pragma unroll
                for (int nb = 0; nb < 8; nb++)
                    mma16816(acc[mt][nb], a[mt], b[nb >> 1][(nb & 1) * 2], b[nb >> 1][(nb & 1) * 2 + 1]);
        }
        __syncthreads();
        if (ch + 2 < NCH) load_chunk(tid, m0, ng, ch + 2, sA[buf], sB[buf]);
    }

    const int w  = ng >> 9;
    const int o0 = (ng & 511) + wn * 64;
    const float* __restrict__ bv = p.b[w];
    const int qrow = lane >> 2;
    const int qcol = (lane & 3) * 2;
    #pragma unroll
    for (int mt = 0; mt < 2; mt++) {
        const int r0 = m0 + wm * 32 + mt * 16 + qrow;
        #pragma unroll
        for (int nb = 0; nb < 8; nb++) {
            const int col = o0 + nb * 8 + qcol;
            const float2 b2 = *(const float2*)&bv[col];
            float* d0 = &g_proj[((size_t)w * MM + r0) * DD + col];
            float* d1 = &g_proj[((size_t)w * MM + r0 + 8) * DD + col];
            ((float2*)d0)[0] = {acc[mt][nb][0] + b2.x, acc[mt][nb][1] + b2.y};
            ((float2*)d1)[0] = {acc[mt][nb][2] + b2.x, acc[mt][nb][3] + b2.y};
        }
    }
}

// ---------------------------------------------------------------------------
// attn: hybrid MUFU + packed-f32x2 polynomial exp2
// ---------------------------------------------------------------------------
struct ExpConsts {
    ull c2p, nm2p, magic2, neg1, c5, c4, c3, c2, c1, c0;
};

__device__ __forceinline__ void mufu_pair(ull k2, ull v2, const ExpConsts& E, ull& Z, ull& S) {
    ull arg = f2fma(E.c2p, k2, E.nm2p);
    float e0 = ex2f(lo32(arg));
    float e1 = ex2f(hi32(arg));
    ull e2 = pack2(e0, e1);
    Z = f2add(Z, e2);
    S = f2fma(e2, v2, S);
}

__device__ __forceinline__ void poly_pair(ull k2, ull v2, const ExpConsts& E, ull& Z, ull& S) {
    ull arg = f2fma(E.c2p, k2, E.nm2p);
    ull tm  = f2add(arg, E.magic2);             // round-to-nearest int encoded in mantissa
    ull n   = f2fma(E.magic2, E.neg1, tm);      // n = tm - magic (exact)
    ull f   = f2fma(n, E.neg1, arg);            // f = arg - n, |f| <= 0.5
    ull p   = f2fma(E.c5, f, E.c4);             // 2^f, degree-5 Taylor (err < 3e-6)
    p = f2fma(p, f, E.c3);
    p = f2fma(p, f, E.c2);
    p = f2fma(p, f, E.c1);
    p = f2fma(p, f, E.c0);
    uint32_t tlo = (uint32_t)tm, thi = (uint32_t)(tm >> 32);
    uint32_t plo = (uint32_t)p,  phi = (uint32_t)(p >> 32);
    ull e2 = pack2(__uint_as_float(plo + (tlo << 23)),
                   __uint_as_float(phi + (thi << 23)));
    Z = f2add(Z, e2);
    S = f2fma(e2, v2, S);
}

__global__ __launch_bounds__(512) void attn_kernel(float* __restrict__ out) {
    const int m    = blockIdx.x;
    const int i    = threadIdx.x;
    const int lane = i & 31;
    const int wid  = i >> 5;
    const float LOG2E = 1.4426950408889634f;

    const float* __restrict__ Qf = g_proj + (size_t)0 * MM * DD + (size_t)m * DD;
    const float* __restrict__ Kf = g_proj + (size_t)1 * MM * DD + (size_t)m * DD;
    const float* __restrict__ Vf = g_proj + (size_t)2 * MM * DD + (size_t)m * DD;
    const float* __restrict__ Qt = g_proj + (size_t)3 * MM * DD + (size_t)m * DD;
    const float* __restrict__ Kt = g_proj + (size_t)4 * MM * DD + (size_t)m * DD;
    const float* __restrict__ Vt = g_proj + (size_t)5 * MM * DD + (size_t)m * DD;

    __shared__ __align__(16) float sK[DD];
    __shared__ __align__(16) float sV[DD];
    __shared__ float redA[16], redB[16], redC[16];

    const float kt = Kt[i];
    const float vt = Vt[i];
    sK[i] = kt;
    sV[i] = vt;
    const float s  = Qf[i] * Kf[i];
    const float vf = Vf[i];
    const float c  = Qt[i];

    float smax = s, kmax = kt, kmin = kt;
    #pragma unroll
    for (int off = 16; off; off >>= 1) {
        smax = fmaxf(smax, __shfl_xor_sync(0xffffffffu, smax, off));
        kmax = fmaxf(kmax, __shfl_xor_sync(0xffffffffu, kmax, off));
        kmin = fminf(kmin, __shfl_xor_sync(0xffffffffu, kmin, off));
    }
    if (lane == 0) { redA[wid] = smax; redB[wid] = kmax; redC[wid] = kmin; }
    __syncthreads();
    smax = redA[0]; kmax = redB[0]; kmin = redC[0];
    #pragma unroll
    for (int t = 1; t < 16; t++) {
        smax = fmaxf(smax, redA[t]);
        kmax = fmaxf(kmax, redB[t]);
        kmin = fminf(kmin, redC[t]);
    }
    __syncthreads();

    const float e = ex2f((s - smax) * LOG2E);
    float zf = e;
    #pragma unroll
    for (int off = 16; off; off >>= 1)
        zf += __shfl_xor_sync(0xffffffffu, zf, off);
    if (lane == 0) redA[wid] = zf;
    __syncthreads();
    zf = redA[0];
    #pragma unroll
    for (int t = 1; t < 16; t++) zf += redA[t];

    const float ctx_f = (e / zf) * vf;

    // temporal branch, log2 domain
    const float c2 = c * LOG2E;
    const float m2 = (c >= 0.f) ? c2 * kmax : c2 * kmin;   // exact row max (log2)
    const float nm2 = -m2;

    ExpConsts E;
    E.c2p    = pack2(c2, c2);
    E.nm2p   = pack2(nm2, nm2);
    E.magic2 = pack2(12582912.0f, 12582912.0f);
    E.neg1   = pack2(-1.0f, -1.0f);
    E.c5 = pack2(0.0013333558f, 0.0013333558f);
    E.c4 = pack2(0.0096181291f, 0.0096181291f);
    E.c3 = pack2(0.0555041087f, 0.0555041087f);
    E.c2 = pack2(0.2402265070f, 0.2402265070f);
    E.c1 = pack2(0.6931471806f, 0.6931471806f);
    E.c0 = pack2(1.0f, 1.0f);

    ull Zm = 0ull, Sm = 0ull, Zp = 0ull, Sp = 0ull;   // bits 0 == {0.f,0.f}
    #pragma unroll 1
    for (int j = 0; j < DD; j += 16) {
        const ulonglong2 ka = *(const ulonglong2*)&sK[j];
        const ulonglong2 kb = *(const ulonglong2*)&sK[j + 4];
        const ulonglong2 kc = *(const ulonglong2*)&sK[j + 8];
        const ulonglong2 kd = *(const ulonglong2*)&sK[j + 12];
        const ulonglong2 va = *(const ulonglong2*)&sV[j];
        const ulonglong2 vb = *(const ulonglong2*)&sV[j + 4];
        const ulonglong2 vc = *(const ulonglong2*)&sV[j + 8];
        const ulonglong2 vd = *(const ulonglong2*)&sV[j + 12];
        // 10 elems on MUFU, 6 elems on fma-pipe poly (pipe-balance ratio)
        mufu_pair(ka.x, va.x, E, Zm, Sm);
        mufu_pair(ka.y, va.y, E, Zm, Sm);
        mufu_pair(kb.x, vb.x, E, Zm, Sm);
        mufu_pair(kb.y, vb.y, E, Zm, Sm);
        mufu_pair(kc.x, vc.x, E, Zm, Sm);
        poly_pair(kc.y, vc.y, E, Zp, Sp);
        poly_pair(kd.x, vd.x, E, Zp, Sp);
        poly_pair(kd.y, vd.y, E, Zp, Sp);
    }
    const float Z = (lo32(Zm) + hi32(Zm)) + (lo32(Zp) + hi32(Zp));
    const float S = (lo32(Sm) + hi32(Sm)) + (lo32(Sp) + hi32(Sp));

    out[(size_t)m * DD + i] = ctx_f + S / Z;
}

extern "C" void kernel_launch(void* const* d_in, const int* in_sizes, int n_in,
                              void* d_out, int out_size) {
    (void)in_sizes; (void)n_in; (void)out_size;
    const float* x = (const float*)d_in[0];
    WPtrs p;
    for (int w = 0; w < NWT; w++) {
        p.W[w] = (const float*)d_in[1 + 2 * w];
        p.b[w] = (const float*)d_in[2 + 2 * w];
    }
    cudaFuncSetAttribute(gemm_mma, cudaFuncAttributeMaxDynamicSharedMemorySize, GSMEM);
    conv_x<<<512, 256>>>(x);
    conv_w<<<1536, 256>>>(p);
    gemm_mma<<<dim3(MM / MT, NN / NT), 256, GSMEM>>>(p);
    attn_kernel<<<MM, 512>>>((float*)d_out);
}

// round 5
// speedup vs baseline: 1.8514x; 1.8514x over previous
#include <cuda_runtime.h>
#include <cuda_bf16.h>
#include <cstdint>

#define BB 8
#define TT 128
#define DD 512
#define MM (BB*TT)          // 1024 tokens
#define NWT 6
#define NN (NWT*DD)         // 3072 total output cols
#define KP 1536             // split-K': [hi|hi|lo] x [hi|lo|hi]
#define KC 64
#define NCH (KP/KC)         // 24 chunks
#define MT 128
#define NT 128
#define GSMEM (64*1024)
#define NB 16               // temporal buckets == warps per CTA
#define ND 7                // Taylor terms (degree 6)

__device__ float g_proj[NWT * MM * DD];
__device__ __nv_bfloat16 gA[(size_t)MM * KP];
__device__ __nv_bfloat16 gB[(size_t)NN * KP];

struct WPtrs { const float* W[NWT]; const float* b[NWT]; };

// ---------------------------------------------------------------------------
__device__ __forceinline__ uint32_t smem_u32(const void* p) {
    uint32_t a;
    asm("{ .reg .u64 t; cvta.to.shared.u64 t, %1; cvt.u32.u64 %0, t; }" : "=r"(a) : "l"(p));
    return a;
}
__device__ __forceinline__ void cp16(uint32_t saddr, const void* g) {
    asm volatile("cp.async.cg.shared.global [%0], [%1], 16;" :: "r"(saddr), "l"(g));
}
__device__ __forceinline__ void cp_commit() { asm volatile("cp.async.commit_group;" ::: "memory"); }
__device__ __forceinline__ void cp_wait1()  { asm volatile("cp.async.wait_group 1;" ::: "memory"); }
__device__ __forceinline__ void cp_wait0()  { asm volatile("cp.async.wait_group 0;" ::: "memory"); }
__device__ __forceinline__ void ldsm4(uint32_t* d, uint32_t a) {
    asm volatile("ldmatrix.sync.aligned.m8n8.x4.shared.b16 {%0,%1,%2,%3}, [%4];"
        : "=r"(d[0]), "=r"(d[1]), "=r"(d[2]), "=r"(d[3]) : "r"(a));
}
__device__ __forceinline__ void mma16816(float* c, const uint32_t* a, uint32_t b0, uint32_t b1) {
    asm volatile(
        "mma.sync.aligned.m16n8k16.row.col.f32.bf16.bf16.f32 "
        "{%0,%1,%2,%3}, {%4,%5,%6,%7}, {%8,%9}, {%0,%1,%2,%3};"
        : "+f"(c[0]), "+f"(c[1]), "+f"(c[2]), "+f"(c[3])
        : "r"(a[0]), "r"(a[1]), "r"(a[2]), "r"(a[3]), "r"(b0), "r"(b1));
}
__device__ __forceinline__ float ex2f(float x) { float y; asm("ex2.approx.f32 %0, %1;" : "=f"(y) : "f"(x)); return y; }

#define SW128(o) ((o) ^ (((o) >> 3) & 0x70))

// ---------------------------------------------------------------------------
// fp32 -> bf16 hi/lo split & pack
// ---------------------------------------------------------------------------
__global__ __launch_bounds__(256) void conv_x(const float* __restrict__ x) {
    int idx = blockIdx.x * 256 + threadIdx.x;
    int m = idx >> 7;
    int k4 = (idx & 127) << 2;
    float4 v = *(const float4*)&x[(size_t)m * DD + k4];
    __nv_bfloat16 h[4], l[4];
    float vv[4] = {v.x, v.y, v.z, v.w};
    #pragma unroll
    for (int i = 0; i < 4; i++) {
        h[i] = __float2bfloat16_rn(vv[i]);
        l[i] = __float2bfloat16_rn(vv[i] - __bfloat162float(h[i]));
    }
    __nv_bfloat162* p0 = (__nv_bfloat162*)&gA[(size_t)m * KP + k4];
    p0[0] = {h[0], h[1]}; p0[1] = {h[2], h[3]};
    __nv_bfloat162* p1 = (__nv_bfloat162*)&gA[(size_t)m * KP + 512 + k4];
    p1[0] = {h[0], h[1]}; p1[1] = {h[2], h[3]};
    __nv_bfloat162* p2 = (__nv_bfloat162*)&gA[(size_t)m * KP + 1024 + k4];
    p2[0] = {l[0], l[1]}; p2[1] = {l[2], l[3]};
}

__global__ __launch_bounds__(256) void conv_w(WPtrs p) {
    int idx = blockIdx.x * 256 + threadIdx.x;
    int flat = idx << 2;
    int w = flat >> 18;
    int o = (flat >> 9) & 511;
    int k4 = flat & 511;
    float4 v = *(const float4*)&p.W[w][(size_t)o * DD + k4];
    __nv_bfloat16 h[4], l[4];
    float vv[4] = {v.x, v.y, v.z, v.w};
    #pragma unroll
    for (int i = 0; i < 4; i++) {
        h[i] = __float2bfloat16_rn(vv[i]);
        l[i] = __float2bfloat16_rn(vv[i] - __bfloat162float(h[i]));
    }
    size_t row = (size_t)(w * DD + o) * KP;
    __nv_bfloat162* p0 = (__nv_bfloat162*)&gB[row + k4];
    p0[0] = {h[0], h[1]}; p0[1] = {h[2], h[3]};
    __nv_bfloat162* p1 = (__nv_bfloat162*)&gB[row + 512 + k4];
    p1[0] = {l[0], l[1]}; p1[1] = {l[2], l[3]};
    __nv_bfloat162* p2 = (__nv_bfloat162*)&gB[row + 1024 + k4];
    p2[0] = {h[0], h[1]}; p2[1] = {h[2], h[3]};
}

// ---------------------------------------------------------------------------
// mma.sync GEMM (unchanged from R3: passing @ rel_err 6.4e-6)
// ---------------------------------------------------------------------------
__device__ __forceinline__ void load_chunk(int tid, int m0, int ng, int c,
                                           uint32_t sAb, uint32_t sBb) {
    const int kb = c * KC;
    #pragma unroll
    for (int t = 0; t < 4; t++) {
        int idx = tid + t * 256;
        int row = idx >> 3, c16 = idx & 7;
        const char* ga = (const char*)gA + ((size_t)(m0 + row) * KP + kb) * 2 + c16 * 16;
        cp16(sAb + SW128(row * 128 + c16 * 16), ga);
    }
    #pragma unroll
    for (int t = 0; t < 4; t++) {
        int idx = tid + t * 256;
        int row = idx >> 3, c16 = idx & 7;
        const char* gb = (const char*)gB + ((size_t)(ng + row) * KP + kb) * 2 + c16 * 16;
        cp16(sBb + SW128(row * 128 + c16 * 16), gb);
    }
    cp_commit();
}

__global__ __launch_bounds__(256, 2) void gemm_mma(WPtrs p) {
    extern __shared__ __align__(1024) char dsm[];
    const uint32_t sbase = smem_u32(dsm);
    const uint32_t sA[2] = {sbase,            sbase + 16384u};
    const uint32_t sB[2] = {sbase + 32768u,   sbase + 49152u};

    const int tid  = threadIdx.x;
    const int wid  = tid >> 5, lane = tid & 31;
    const int wm   = wid & 3;
    const int wn   = wid >> 2;
    const int m0 = blockIdx.x * MT;
    const int ng = blockIdx.y * NT;

    float acc[2][8][4];
    #pragma unroll
    for (int i = 0; i < 2; i++)
        #pragma unroll
        for (int j = 0; j < 8; j++)
            #pragma unroll
            for (int q = 0; q < 4; q++) acc[i][j][q] = 0.f;

    load_chunk(tid, m0, ng, 0, sA[0], sB[0]);
    load_chunk(tid, m0, ng, 1, sA[1], sB[1]);

    const int a_row  = wm * 32 + (lane & 15);
    const int a_koff = ((lane >> 4) << 3) * 2;
    const int b_row  = wn * 64 + (lane & 7) + ((lane >> 4) << 3);
    const int b_koff = (((lane >> 3) & 1) << 3) * 2;

    for (int ch = 0; ch < NCH; ch++) {
        const int buf = ch & 1;
        if (ch < NCH - 1) cp_wait1(); else cp_wait0();
        __syncthreads();

        #pragma unroll
        for (int ks = 0; ks < 4; ks++) {
            const int kb = ks * 32;
            uint32_t a[2][4];
            #pragma unroll
            for (int mt = 0; mt < 2; mt++)
                ldsm4(a[mt], sA[buf] + SW128((a_row + mt * 16) * 128 + kb + a_koff));
            uint32_t b[4][4];
            #pragma unroll
            for (int nt = 0; nt < 4; nt++)
                ldsm4(b[nt], sB[buf] + SW128((b_row + nt * 16) * 128 + kb + b_koff));
            #pragma unroll
            for (int mt = 0; mt < 2; mt++)
                #pragma unroll
                for (int nb = 0; nb < 8; nb++)
                    mma16816(acc[mt][nb], a[mt], b[nb >> 1][(nb & 1) * 2], b[nb >> 1][(nb & 1) * 2 + 1]);
        }
        __syncthreads();
        if (ch + 2 < NCH) load_chunk(tid, m0, ng, ch + 2, sA[buf], sB[buf]);
    }

    const int w  = ng >> 9;
    const int o0 = (ng & 511) + wn * 64;
    const float* __restrict__ bv = p.b[w];
    const int qrow = lane >> 2;
    const int qcol = (lane & 3) * 2;
    #pragma unroll
    for (int mt = 0; mt < 2; mt++) {
        const int r0 = m0 + wm * 32 + mt * 16 + qrow;
        #pragma unroll
        for (int nb = 0; nb < 8; nb++) {
            const int col = o0 + nb * 8 + qcol;
            const float2 b2 = *(const float2*)&bv[col];
            float* d0 = &g_proj[((size_t)w * MM + r0) * DD + col];
            float* d1 = &g_proj[((size_t)w * MM + r0 + 8) * DD + col];
            ((float2*)d0)[0] = {acc[mt][nb][0] + b2.x, acc[mt][nb][1] + b2.y};
            ((float2*)d1)[0] = {acc[mt][nb][2] + b2.x, acc[mt][nb][3] + b2.y};
        }
    }
}

// ---------------------------------------------------------------------------
// attn: bucketed-moment temporal softmax (O(D*NB) instead of O(D^2))
//   e^{c_i k_j} = e^{c0_b k_j} * e^{d k_j},  d = c_i - c0_b, |d*k| <= ~0.35
//   num_i = sum_n d^n/n! * M_n(b),  den_i = sum_n d^n/n! * A_n(b)
//   M_n(b) = sum_j e^{c0_b k_j} k_j^n v_j,  A_n likewise with v=1.
// Warp w computes bucket w's moments (lane-strided over j), then every
// thread evaluates its Horner polynomial from its bucket's moments.
// ---------------------------------------------------------------------------
__global__ __launch_bounds__(512) void attn_kernel(float* __restrict__ out) {
    const int m    = blockIdx.x;
    const int i    = threadIdx.x;
    const int lane = i & 31;
    const int wid  = i >> 5;     // 16 warps == NB buckets
    const float LOG2E = 1.4426950408889634f;

    const float* __restrict__ Qf = g_proj + (size_t)0 * MM * DD + (size_t)m * DD;
    const float* __restrict__ Kf = g_proj + (size_t)1 * MM * DD + (size_t)m * DD;
    const float* __restrict__ Vf = g_proj + (size_t)2 * MM * DD + (size_t)m * DD;
    const float* __restrict__ Qt = g_proj + (size_t)3 * MM * DD + (size_t)m * DD;
    const float* __restrict__ Kt = g_proj + (size_t)4 * MM * DD + (size_t)m * DD;
    const float* __restrict__ Vt = g_proj + (size_t)5 * MM * DD + (size_t)m * DD;

    __shared__ __align__(16) float sK[DD];
    __shared__ __align__(16) float sV[DD];
    __shared__ float sMA[NB][ND + 1];   // denominator moments (pad to 8)
    __shared__ float sMM[NB][ND + 1];   // numerator moments
    __shared__ float redA[16], redB[16], redC[16];

    const float kt = Kt[i];
    sK[i] = kt;
    sV[i] = Vt[i];
    const float s  = Qf[i] * Kf[i];
    const float vf = Vf[i];
    const float c  = Qt[i];

    // joint reduction: max(s), min(c), max(c)
    float smax = s, cmin = c, cmax = c;
    #pragma unroll
    for (int off = 16; off; off >>= 1) {
        smax = fmaxf(smax, __shfl_xor_sync(0xffffffffu, smax, off));
        cmin = fminf(cmin, __shfl_xor_sync(0xffffffffu, cmin, off));
        cmax = fmaxf(cmax, __shfl_xor_sync(0xffffffffu, cmax, off));
    }
    if (lane == 0) { redA[wid] = smax; redB[wid] = cmin; redC[wid] = cmax; }
    __syncthreads();   // also publishes sK / sV
    smax = redA[0]; cmin = redB[0]; cmax = redC[0];
    #pragma unroll
    for (int t = 1; t < 16; t++) {
        smax = fmaxf(smax, redA[t]);
        cmin = fminf(cmin, redB[t]);
        cmax = fmaxf(cmax, redC[t]);
    }
    __syncthreads();   // protect redA before reuse

    // feature-branch softmax denominator
    const float e = ex2f((s - smax) * LOG2E);
    float zf = e;
    #pragma unroll
    for (int off = 16; off; off >>= 1)
        zf += __shfl_xor_sync(0xffffffffu, zf, off);
    if (lane == 0) redA[wid] = zf;
    __syncthreads();
    zf = redA[0];
    #pragma unroll
    for (int t = 1; t < 16; t++) zf += redA[t];
    const float ctx_f = (e / zf) * vf;

    // ---- temporal phase 1: bucket moments (warp wid == bucket wid) ----
    const float bw = (cmax - cmin) * (1.0f / NB);
    const float c0 = fmaf((float)wid + 0.5f, bw, cmin);
    const float c0l = c0 * LOG2E;

    float a[ND], mm[ND];
    #pragma unroll
    for (int n = 0; n < ND; n++) { a[n] = 0.f; mm[n] = 0.f; }

    #pragma unroll 4
    for (int jj = 0; jj < DD / 32; jj++) {
        const int j = jj * 32 + lane;
        const float k = sK[j];
        const float v = sV[j];
        float p = ex2f(c0l * k);      // e^{c0 * k}
        #pragma unroll
        for (int n = 0; n < ND; n++) {
            a[n]  += p;
            mm[n]  = fmaf(p, v, mm[n]);
            if (n < ND - 1) p *= k;
        }
    }
    #pragma unroll
    for (int n = 0; n < ND; n++) {
        float av = a[n], mv = mm[n];
        #pragma unroll
        for (int off = 16; off; off >>= 1) {
            av += __shfl_xor_sync(0xffffffffu, av, off);
            mv += __shfl_xor_sync(0xffffffffu, mv, off);
        }
        if (lane == 0) { sMA[wid][n] = av; sMM[wid][n] = mv; }
    }
    __syncthreads();

    // ---- temporal phase 2: per-thread Horner in d = c - c0_b ----
    const float W   = cmax - cmin;
    const float sc  = (W > 0.f) ? ((float)NB / W) : 0.f;
    int b = (int)((c - cmin) * sc);
    b = (b > NB - 1) ? NB - 1 : ((b < 0) ? 0 : b);
    const float d = c - fmaf((float)b + 0.5f, bw, cmin);

    const float IF[ND] = {1.f, 1.f, 0.5f, 1.f/6.f, 1.f/24.f, 1.f/120.f, 1.f/720.f};
    const float* MA = sMA[b];
    const float* MMp = sMM[b];
    float den = MA[ND - 1] * IF[ND - 1];
    float num = MMp[ND - 1] * IF[ND - 1];
    #pragma unroll
    for (int n = ND - 2; n >= 0; n--) {
        den = fmaf(den, d, MA[n] * IF[n]);
        num = fmaf(num, d, MMp[n] * IF[n]);
    }

    out[(size_t)m * DD + i] = ctx_f + num / den;
}

extern "C" void kernel_launch(void* const* d_in, const int* in_sizes, int n_in,
                              void* d_out, int out_size) {
    (void)in_sizes; (void)n_in; (void)out_size;
    const float* x = (const float*)d_in[0];
    WPtrs p;
    for (int w = 0; w < NWT; w++) {
        p.W[w] = (const float*)d_in[1 + 2 * w];
        p.b[w] = (const float*)d_in[2 + 2 * w];
    }
    cudaFuncSetAttribute(gemm_mma, cudaFuncAttributeMaxDynamicSharedMemorySize, GSMEM);
    conv_x<<<512, 256>>>(x);
    conv_w<<<1536, 256>>>(p);
    gemm_mma<<<dim3(MM / MT, NN / NT), 256, GSMEM>>>(p);
    attn_kernel<<<MM, 512>>>((float*)d_out);
}

// round 6
// speedup vs baseline: 1.8622x; 1.0058x over previous
#include <cuda_runtime.h>
#include <cuda_bf16.h>
#include <cstdint>

#define BB 8
#define TT 128
#define DD 512
#define MM (BB*TT)          // 1024 tokens
#define NWT 6
#define NN (NWT*DD)         // 3072 total output cols
#define KP 1536             // split-K': [hi|hi|lo] x [hi|lo|hi]
#define KC 64
#define NCH (KP/KC)         // 24 chunks
#define MT 128
#define NT 128
#define NSTG 3
#define STG_BYTES 32768     // A 16KB + B 16KB per stage
#define GSMEM (NSTG*STG_BYTES)
#define NB 16               // temporal buckets == warps per CTA
#define ND 6                // Taylor terms (degree 5)

__device__ float g_proj[NWT * MM * DD];
__device__ __nv_bfloat16 gA[(size_t)MM * KP];
__device__ __nv_bfloat16 gB[(size_t)NN * KP];

struct WPtrs { const float* W[NWT]; const float* b[NWT]; };

// ---------------------------------------------------------------------------
__device__ __forceinline__ uint32_t smem_u32(const void* p) {
    uint32_t a;
    asm("{ .reg .u64 t; cvta.to.shared.u64 t, %1; cvt.u32.u64 %0, t; }" : "=r"(a) : "l"(p));
    return a;
}
__device__ __forceinline__ void cp16(uint32_t saddr, const void* g) {
    asm volatile("cp.async.cg.shared.global [%0], [%1], 16;" :: "r"(saddr), "l"(g));
}
__device__ __forceinline__ void cp_commit() { asm volatile("cp.async.commit_group;" ::: "memory"); }
__device__ __forceinline__ void cp_wait1()  { asm volatile("cp.async.wait_group 1;" ::: "memory"); }
__device__ __forceinline__ void ldsm4(uint32_t* d, uint32_t a) {
    asm volatile("ldmatrix.sync.aligned.m8n8.x4.shared.b16 {%0,%1,%2,%3}, [%4];"
        : "=r"(d[0]), "=r"(d[1]), "=r"(d[2]), "=r"(d[3]) : "r"(a));
}
__device__ __forceinline__ void mma16816(float* c, const uint32_t* a, uint32_t b0, uint32_t b1) {
    asm volatile(
        "mma.sync.aligned.m16n8k16.row.col.f32.bf16.bf16.f32 "
        "{%0,%1,%2,%3}, {%4,%5,%6,%7}, {%8,%9}, {%0,%1,%2,%3};"
        : "+f"(c[0]), "+f"(c[1]), "+f"(c[2]), "+f"(c[3])
        : "r"(a[0]), "r"(a[1]), "r"(a[2]), "r"(a[3]), "r"(b0), "r"(b1));
}
__device__ __forceinline__ float ex2f(float x) { float y; asm("ex2.approx.f32 %0, %1;" : "=f"(y) : "f"(x)); return y; }

#define SW128(o) ((o) ^ (((o) >> 3) & 0x70))

// ---------------------------------------------------------------------------
// fused fp32 -> bf16 hi/lo split & pack (x and all W in one launch)
// ---------------------------------------------------------------------------
__global__ __launch_bounds__(256) void conv_all(const float* __restrict__ x, WPtrs p) {
    const int blk = blockIdx.x;
    if (blk < 512) {                     // ---- x path: 512 blocks
        int idx = blk * 256 + threadIdx.x;
        int m = idx >> 7;
        int k4 = (idx & 127) << 2;
        float4 v = *(const float4*)&x[(size_t)m * DD + k4];
        __nv_bfloat16 h[4], l[4];
        float vv[4] = {v.x, v.y, v.z, v.w};
        #pragma unroll
        for (int i = 0; i < 4; i++) {
            h[i] = __float2bfloat16_rn(vv[i]);
            l[i] = __float2bfloat16_rn(vv[i] - __bfloat162float(h[i]));
        }
        __nv_bfloat162* p0 = (__nv_bfloat162*)&gA[(size_t)m * KP + k4];
        p0[0] = {h[0], h[1]}; p0[1] = {h[2], h[3]};
        __nv_bfloat162* p1 = (__nv_bfloat162*)&gA[(size_t)m * KP + 512 + k4];
        p1[0] = {h[0], h[1]}; p1[1] = {h[2], h[3]};
        __nv_bfloat162* p2 = (__nv_bfloat162*)&gA[(size_t)m * KP + 1024 + k4];
        p2[0] = {l[0], l[1]}; p2[1] = {l[2], l[3]};
    } else {                             // ---- W path: 1536 blocks
        int idx = (blk - 512) * 256 + threadIdx.x;
        int flat = idx << 2;
        int w = flat >> 18;
        int o = (flat >> 9) & 511;
        int k4 = flat & 511;
        float4 v = *(const float4*)&p.W[w][(size_t)o * DD + k4];
        __nv_bfloat16 h[4], l[4];
        float vv[4] = {v.x, v.y, v.z, v.w};
        #pragma unroll
        for (int i = 0; i < 4; i++) {
            h[i] = __float2bfloat16_rn(vv[i]);
            l[i] = __float2bfloat16_rn(vv[i] - __bfloat162float(h[i]));
        }
        size_t row = (size_t)(w * DD + o) * KP;
        __nv_bfloat162* p0 = (__nv_bfloat162*)&gB[row + k4];
        p0[0] = {h[0], h[1]}; p0[1] = {h[2], h[3]};
        __nv_bfloat162* p1 = (__nv_bfloat162*)&gB[row + 512 + k4];
        p1[0] = {l[0], l[1]}; p1[1] = {l[2], l[3]};
        __nv_bfloat162* p2 = (__nv_bfloat162*)&gB[row + 1024 + k4];
        p2[0] = {h[0], h[1]}; p2[1] = {h[2], h[3]};
    }
}

// ---------------------------------------------------------------------------
// mma.sync GEMM, 3-stage cp.async pipeline, one __syncthreads per k-chunk
// ---------------------------------------------------------------------------
__device__ __forceinline__ void load_chunk(int tid, int m0, int ng, int c, uint32_t stg) {
    const int kb = c * KC;
    const uint32_t sAb = stg, sBb = stg + 16384u;
    #pragma unroll
    for (int t = 0; t < 4; t++) {
        int idx = tid + t * 256;
        int row = idx >> 3, c16 = idx & 7;
        const char* ga = (const char*)gA + ((size_t)(m0 + row) * KP + kb) * 2 + c16 * 16;
        cp16(sAb + SW128(row * 128 + c16 * 16), ga);
    }
    #pragma unroll
    for (int t = 0; t < 4; t++) {
        int idx = tid + t * 256;
        int row = idx >> 3, c16 = idx & 7;
        const char* gb = (const char*)gB + ((size_t)(ng + row) * KP + kb) * 2 + c16 * 16;
        cp16(sBb + SW128(row * 128 + c16 * 16), gb);
    }
    cp_commit();
}

__global__ __launch_bounds__(256, 2) void gemm_mma(WPtrs p) {
    extern __shared__ __align__(1024) char dsm[];
    const uint32_t sbase = smem_u32(dsm);

    const int tid  = threadIdx.x;
    const int wid  = tid >> 5, lane = tid & 31;
    const int wm   = wid & 3;
    const int wn   = wid >> 2;
    const int m0 = blockIdx.x * MT;
    const int ng = blockIdx.y * NT;

    float acc[2][8][4];
    #pragma unroll
    for (int i = 0; i < 2; i++)
        #pragma unroll
        for (int j = 0; j < 8; j++)
            #pragma unroll
            for (int q = 0; q < 4; q++) acc[i][j][q] = 0.f;

    load_chunk(tid, m0, ng, 0, sbase);
    load_chunk(tid, m0, ng, 1, sbase + STG_BYTES);

    const int a_row  = wm * 32 + (lane & 15);
    const int a_koff = ((lane >> 4) << 3) * 2;
    const int b_row  = wn * 64 + (lane & 7) + ((lane >> 4) << 3);
    const int b_koff = (((lane >> 3) & 1) << 3) * 2;

    int slot = 0;                 // ch % 3
    int nslot = 2;                // (ch+2) % 3
    for (int ch = 0; ch < NCH; ch++) {
        cp_wait1();               // tile ch resident (groups <= ch complete)
        __syncthreads();          // all warps done with slot (ch-1)%3 == nslot

        if (ch + 2 < NCH) load_chunk(tid, m0, ng, ch + 2, sbase + nslot * STG_BYTES);
        else cp_commit();         // keep group count in lockstep

        const uint32_t sAb = sbase + slot * STG_BYTES;
        const uint32_t sBb = sAb + 16384u;
        #pragma unroll
        for (int ks = 0; ks < 4; ks++) {
            const int kb = ks * 32;
            uint32_t a[2][4];
            #pragma unroll
            for (int mt = 0; mt < 2; mt++)
                ldsm4(a[mt], sAb + SW128((a_row + mt * 16) * 128 + kb + a_koff));
            uint32_t b[4][4];
            #pragma unroll
            for (int nt = 0; nt < 4; nt++)
                ldsm4(b[nt], sBb + SW128((b_row + nt * 16) * 128 + kb + b_koff));
            #pragma unroll
            for (int mt = 0; mt < 2; mt++)
                #pragma unroll
                for (int nb = 0; nb < 8; nb++)
                    mma16816(acc[mt][nb], a[mt], b[nb >> 1][(nb & 1) * 2], b[nb >> 1][(nb & 1) * 2 + 1]);
        }
        nslot = slot;
        slot = (slot == 2) ? 0 : slot + 1;
    }

    const int w  = ng >> 9;
    const int o0 = (ng & 511) + wn * 64;
    const float* __restrict__ bv = p.b[w];
    const int qrow = lane >> 2;
    const int qcol = (lane & 3) * 2;
    #pragma unroll
    for (int mt = 0; mt < 2; mt++) {
        const int r0 = m0 + wm * 32 + mt * 16 + qrow;
        #pragma unroll
        for (int nb = 0; nb < 8; nb++) {
            const int col = o0 + nb * 8 + qcol;
            const float2 b2 = *(const float2*)&bv[col];
            float* d0 = &g_proj[((size_t)w * MM + r0) * DD + col];
            float* d1 = &g_proj[((size_t)w * MM + r0 + 8) * DD + col];
            ((float2*)d0)[0] = {acc[mt][nb][0] + b2.x, acc[mt][nb][1] + b2.y};
            ((float2*)d1)[0] = {acc[mt][nb][2] + b2.x, acc[mt][nb][3] + b2.y};
        }
    }
}

// ---------------------------------------------------------------------------
// attn: bucketed-moment temporal softmax, 2-way ILP moment loop, ND=6
// ---------------------------------------------------------------------------
__global__ __launch_bounds__(512) void attn_kernel(float* __restrict__ out) {
    const int m    = blockIdx.x;
    const int i    = threadIdx.x;
    const int lane = i & 31;
    const int wid  = i >> 5;     // 16 warps == NB buckets
    const float LOG2E = 1.4426950408889634f;

    const float* __restrict__ Qf = g_proj + (size_t)0 * MM * DD + (size_t)m * DD;
    const float* __restrict__ Kf = g_proj + (size_t)1 * MM * DD + (size_t)m * DD;
    const float* __restrict__ Vf = g_proj + (size_t)2 * MM * DD + (size_t)m * DD;
    const float* __restrict__ Qt = g_proj + (size_t)3 * MM * DD + (size_t)m * DD;
    const float* __restrict__ Kt = g_proj + (size_t)4 * MM * DD + (size_t)m * DD;
    const float* __restrict__ Vt = g_proj + (size_t)5 * MM * DD + (size_t)m * DD;

    __shared__ __align__(16) float sK[DD];
    __shared__ __align__(16) float sV[DD];
    __shared__ float sMA[NB][ND + 2];   // pad to 8 floats: bank-spread
    __shared__ float sMM[NB][ND + 2];
    __shared__ float redA[16], redB[16], redC[16];

    const float kt = Kt[i];
    sK[i] = kt;
    sV[i] = Vt[i];
    const float s  = Qf[i] * Kf[i];
    const float vf = Vf[i];
    const float c  = Qt[i];

    float smax = s, cmin = c, cmax = c;
    #pragma unroll
    for (int off = 16; off; off >>= 1) {
        smax = fmaxf(smax, __shfl_xor_sync(0xffffffffu, smax, off));
        cmin = fminf(cmin, __shfl_xor_sync(0xffffffffu, cmin, off));
        cmax = fmaxf(cmax, __shfl_xor_sync(0xffffffffu, cmax, off));
    }
    if (lane == 0) { redA[wid] = smax; redB[wid] = cmin; redC[wid] = cmax; }
    __syncthreads();   // also publishes sK / sV
    smax = redA[0]; cmin = redB[0]; cmax = redC[0];
    #pragma unroll
    for (int t = 1; t < 16; t++) {
        smax = fmaxf(smax, redA[t]);
        cmin = fminf(cmin, redB[t]);
        cmax = fmaxf(cmax, redC[t]);
    }
    __syncthreads();   // protect redA before reuse

    const float e = ex2f((s - smax) * LOG2E);
    float zf = e;
    #pragma unroll
    for (int off = 16; off; off >>= 1)
        zf += __shfl_xor_sync(0xffffffffu, zf, off);
    if (lane == 0) redA[wid] = zf;
    __syncthreads();
    zf = redA[0];
    #pragma unroll
    for (int t = 1; t < 16; t++) zf += redA[t];
    const float ctx_f = (e / zf) * vf;

    // ---- temporal phase 1: bucket moments, 2 independent chains ----
    const float bw = (cmax - cmin) * (1.0f / NB);
    const float c0 = fmaf((float)wid + 0.5f, bw, cmin);
    const float c0l = c0 * LOG2E;

    float a1[ND], m1[ND], a2[ND], m2[ND];
    #pragma unroll
    for (int n = 0; n < ND; n++) { a1[n] = 0.f; m1[n] = 0.f; a2[n] = 0.f; m2[n] = 0.f; }

    #pragma unroll
    for (int jj = 0; jj < DD / 64; jj++) {
        const int j = jj * 64 + lane;
        const float ka = sK[j],      va = sV[j];
        const float kb = sK[j + 32], vb = sV[j + 32];
        float pa = ex2f(c0l * ka);
        float pb = ex2f(c0l * kb);
        #pragma unroll
        for (int n = 0; n < ND; n++) {
            a1[n] += pa;
            a2[n] += pb;
            m1[n]  = fmaf(pa, va, m1[n]);
            m2[n]  = fmaf(pb, vb, m2[n]);
            if (n < ND - 1) { pa *= ka; pb *= kb; }
        }
    }
    #pragma unroll
    for (int n = 0; n < ND; n++) {
        float av = a1[n] + a2[n], mv = m1[n] + m2[n];
        #pragma unroll
        for (int off = 16; off; off >>= 1) {
            av += __shfl_xor_sync(0xffffffffu, av, off);
            mv += __shfl_xor_sync(0xffffffffu, mv, off);
        }
        if (lane == 0) { sMA[wid][n] = av; sMM[wid][n] = mv; }
    }
    __syncthreads();

    // ---- temporal phase 2: per-thread Horner in d = c - c0_b ----
    const float W   = cmax - cmin;
    const float sc  = (W > 0.f) ? ((float)NB / W) : 0.f;
    int b = (int)((c - cmin) * sc);
    b = (b > NB - 1) ? NB - 1 : ((b < 0) ? 0 : b);
    const float d = c - fmaf((float)b + 0.5f, bw, cmin);

    const float IF[ND] = {1.f, 1.f, 0.5f, 1.f/6.f, 1.f/24.f, 1.f/120.f};
    const float* MA  = sMA[b];
    const float* MMp = sMM[b];
    float den = MA[ND - 1] * IF[ND - 1];
    float num = MMp[ND - 1] * IF[ND - 1];
    #pragma unroll
    for (int n = ND - 2; n >= 0; n--) {
        den = fmaf(den, d, MA[n] * IF[n]);
        num = fmaf(num, d, MMp[n] * IF[n]);
    }

    out[(size_t)m * DD + i] = ctx_f + num / den;
}

extern "C" void kernel_launch(void* const* d_in, const int* in_sizes, int n_in,
                              void* d_out, int out_size) {
    (void)in_sizes; (void)n_in; (void)out_size;
    const float* x = (const float*)d_in[0];
    WPtrs p;
    for (int w = 0; w < NWT; w++) {
        p.W[w] = (const float*)d_in[1 + 2 * w];
        p.b[w] = (const float*)d_in[2 + 2 * w];
    }
    cudaFuncSetAttribute(gemm_mma, cudaFuncAttributeMaxDynamicSharedMemorySize, GSMEM);
    conv_all<<<2048, 256>>>(x, p);
    gemm_mma<<<dim3(MM / MT, NN / NT), 256, GSMEM>>>(p);
    attn_kernel<<<MM, 512>>>((float*)d_out);
}

// round 7
// speedup vs baseline: 2.0366x; 1.0937x over previous
#include <cuda_runtime.h>
#include <cuda_bf16.h>
#include <cstdint>

#define BB 8
#define TT 128
#define DD 512
#define MM (BB*TT)          // 1024 tokens
#define NWT 6
#define NN (NWT*DD)         // 3072 total output cols
#define KP 1536             // split-K': [hi|hi|lo] x [hi|lo|hi]
#define KC 64
#define NCH (KP/KC)         // 24 chunks
#define MT 128
#define NT 128
#define NSTG 3
#define STG_BYTES 32768     // A 16KB + B 16KB per stage
#define GSMEM (NSTG*STG_BYTES)
#define NB 8                // temporal buckets (2 warps per bucket)
#define ND 6                // Taylor terms (degree 5)

__device__ float g_proj[NWT * MM * DD];
__device__ __nv_bfloat16 gA[(size_t)MM * KP];
__device__ __nv_bfloat16 gB[(size_t)NN * KP];

struct WPtrs { const float* W[NWT]; const float* b[NWT]; };

// ---------------------------------------------------------------------------
__device__ __forceinline__ uint32_t smem_u32(const void* p) {
    uint32_t a;
    asm("{ .reg .u64 t; cvta.to.shared.u64 t, %1; cvt.u32.u64 %0, t; }" : "=r"(a) : "l"(p));
    return a;
}
__device__ __forceinline__ void cp16(uint32_t saddr, const void* g) {
    asm volatile("cp.async.cg.shared.global [%0], [%1], 16;" :: "r"(saddr), "l"(g));
}
__device__ __forceinline__ void cp_commit() { asm volatile("cp.async.commit_group;" ::: "memory"); }
__device__ __forceinline__ void cp_wait1()  { asm volatile("cp.async.wait_group 1;" ::: "memory"); }
__device__ __forceinline__ void ldsm4(uint32_t* d, uint32_t a) {
    asm volatile("ldmatrix.sync.aligned.m8n8.x4.shared.b16 {%0,%1,%2,%3}, [%4];"
        : "=r"(d[0]), "=r"(d[1]), "=r"(d[2]), "=r"(d[3]) : "r"(a));
}
__device__ __forceinline__ void mma16816(float* c, const uint32_t* a, uint32_t b0, uint32_t b1) {
    asm volatile(
        "mma.sync.aligned.m16n8k16.row.col.f32.bf16.bf16.f32 "
        "{%0,%1,%2,%3}, {%4,%5,%6,%7}, {%8,%9}, {%0,%1,%2,%3};"
        : "+f"(c[0]), "+f"(c[1]), "+f"(c[2]), "+f"(c[3])
        : "r"(a[0]), "r"(a[1]), "r"(a[2]), "r"(a[3]), "r"(b0), "r"(b1));
}
__device__ __forceinline__ float ex2f(float x) { float y; asm("ex2.approx.f32 %0, %1;" : "=f"(y) : "f"(x)); return y; }

#define SW128(o) ((o) ^ (((o) >> 3) & 0x70))

// ---------------------------------------------------------------------------
// fused fp32 -> bf16 hi/lo split & pack, MLP=4 (4 independent loads/thread)
// ---------------------------------------------------------------------------
__global__ __launch_bounds__(256) void conv_all(const float* __restrict__ x, WPtrs p) {
    const int blk = blockIdx.x;
    const int tid = threadIdx.x;
    if (blk < 128) {                      // ---- x path: 128 blocks x 4 f4/thread
        const int base = blk * 1024;
        float4 v[4];
        #pragma unroll
        for (int q = 0; q < 4; q++) {
            int idx = base + q * 256 + tid;
            int m = idx >> 7;
            int k4 = (idx & 127) << 2;
            v[q] = *(const float4*)&x[(size_t)m * DD + k4];
        }
        #pragma unroll
        for (int q = 0; q < 4; q++) {
            int idx = base + q * 256 + tid;
            int m = idx >> 7;
            int k4 = (idx & 127) << 2;
            __nv_bfloat16 h[4], l[4];
            float vv[4] = {v[q].x, v[q].y, v[q].z, v[q].w};
            #pragma unroll
            for (int i = 0; i < 4; i++) {
                h[i] = __float2bfloat16_rn(vv[i]);
                l[i] = __float2bfloat16_rn(vv[i] - __bfloat162float(h[i]));
            }
            __nv_bfloat162* p0 = (__nv_bfloat162*)&gA[(size_t)m * KP + k4];
            p0[0] = {h[0], h[1]}; p0[1] = {h[2], h[3]};
            __nv_bfloat162* p1 = (__nv_bfloat162*)&gA[(size_t)m * KP + 512 + k4];
            p1[0] = {h[0], h[1]}; p1[1] = {h[2], h[3]};
            __nv_bfloat162* p2 = (__nv_bfloat162*)&gA[(size_t)m * KP + 1024 + k4];
            p2[0] = {l[0], l[1]}; p2[1] = {l[2], l[3]};
        }
    } else {                              // ---- W path: 384 blocks x 4 f4/thread
        const int base = (blk - 128) * 1024;
        float4 v[4];
        #pragma unroll
        for (int q = 0; q < 4; q++) {
            int idx = base + q * 256 + tid;
            int flat = idx << 2;
            int w = flat >> 18;
            int o = (flat >> 9) & 511;
            int k4 = flat & 511;
            v[q] = *(const float4*)&p.W[w][(size_t)o * DD + k4];
        }
        #pragma unroll
        for (int q = 0; q < 4; q++) {
            int idx = base + q * 256 + tid;
            int flat = idx << 2;
            int w = flat >> 18;
            int o = (flat >> 9) & 511;
            int k4 = flat & 511;
            __nv_bfloat16 h[4], l[4];
            float vv[4] = {v[q].x, v[q].y, v[q].z, v[q].w};
            #pragma unroll
            for (int i = 0; i < 4; i++) {
                h[i] = __float2bfloat16_rn(vv[i]);
                l[i] = __float2bfloat16_rn(vv[i] - __bfloat162float(h[i]));
            }
            size_t row = (size_t)(w * DD + o) * KP;
            __nv_bfloat162* p0 = (__nv_bfloat162*)&gB[row + k4];
            p0[0] = {h[0], h[1]}; p0[1] = {h[2], h[3]};
            __nv_bfloat162* p1 = (__nv_bfloat162*)&gB[row + 512 + k4];
            p1[0] = {l[0], l[1]}; p1[1] = {l[2], l[3]};
            __nv_bfloat162* p2 = (__nv_bfloat162*)&gB[row + 1024 + k4];
            p2[0] = {h[0], h[1]}; p2[1] = {h[2], h[3]};
        }
    }
}

// ---------------------------------------------------------------------------
// mma.sync GEMM, 3-stage cp.async pipeline, one __syncthreads per k-chunk
// ---------------------------------------------------------------------------
__device__ __forceinline__ void load_chunk(int tid, int m0, int ng, int c, uint32_t stg) {
    const int kb = c * KC;
    const uint32_t sAb = stg, sBb = stg + 16384u;
    #pragma unroll
    for (int t = 0; t < 4; t++) {
        int idx = tid + t * 256;
        int row = idx >> 3, c16 = idx & 7;
        const char* ga = (const char*)gA + ((size_t)(m0 + row) * KP + kb) * 2 + c16 * 16;
        cp16(sAb + SW128(row * 128 + c16 * 16), ga);
    }
    #pragma unroll
    for (int t = 0; t < 4; t++) {
        int idx = tid + t * 256;
        int row = idx >> 3, c16 = idx & 7;
        const char* gb = (const char*)gB + ((size_t)(ng + row) * KP + kb) * 2 + c16 * 16;
        cp16(sBb + SW128(row * 128 + c16 * 16), gb);
    }
    cp_commit();
}

__global__ __launch_bounds__(256, 2) void gemm_mma(WPtrs p) {
    extern __shared__ __align__(1024) char dsm[];
    const uint32_t sbase = smem_u32(dsm);

    const int tid  = threadIdx.x;
    const int wid  = tid >> 5, lane = tid & 31;
    const int wm   = wid & 3;
    const int wn   = wid >> 2;
    const int m0 = blockIdx.x * MT;
    const int ng = blockIdx.y * NT;

    float acc[2][8][4];
    #pragma unroll
    for (int i = 0; i < 2; i++)
        #pragma unroll
        for (int j = 0; j < 8; j++)
            #pragma unroll
            for (int q = 0; q < 4; q++) acc[i][j][q] = 0.f;

    load_chunk(tid, m0, ng, 0, sbase);
    load_chunk(tid, m0, ng, 1, sbase + STG_BYTES);

    const int a_row  = wm * 32 + (lane & 15);
    const int a_koff = ((lane >> 4) << 3) * 2;
    const int b_row  = wn * 64 + (lane & 7) + ((lane >> 4) << 3);
    const int b_koff = (((lane >> 3) & 1) << 3) * 2;

    int slot = 0;
    int nslot = 2;
    for (int ch = 0; ch < NCH; ch++) {
        cp_wait1();
        __syncthreads();

        if (ch + 2 < NCH) load_chunk(tid, m0, ng, ch + 2, sbase + nslot * STG_BYTES);
        else cp_commit();

        const uint32_t sAb = sbase + slot * STG_BYTES;
        const uint32_t sBb = sAb + 16384u;
        #pragma unroll
        for (int ks = 0; ks < 4; ks++) {
            const int kb = ks * 32;
            uint32_t a[2][4];
            #pragma unroll
            for (int mt = 0; mt < 2; mt++)
                ldsm4(a[mt], sAb + SW128((a_row + mt * 16) * 128 + kb + a_koff));
            uint32_t b[4][4];
            #pragma unroll
            for (int nt = 0; nt < 4; nt++)
                ldsm4(b[nt], sBb + SW128((b_row + nt * 16) * 128 + kb + b_koff));
            #pragma unroll
            for (int mt = 0; mt < 2; mt++)
                #pragma unroll
                for (int nb = 0; nb < 8; nb++)
                    mma16816(acc[mt][nb], a[mt], b[nb >> 1][(nb & 1) * 2], b[nb >> 1][(nb & 1) * 2 + 1]);
        }
        nslot = slot;
        slot = (slot == 2) ? 0 : slot + 1;
    }

    const int w  = ng >> 9;
    const int o0 = (ng & 511) + wn * 64;
    const float* __restrict__ bv = p.b[w];
    const int qrow = lane >> 2;
    const int qcol = (lane & 3) * 2;
    #pragma unroll
    for (int mt = 0; mt < 2; mt++) {
        const int r0 = m0 + wm * 32 + mt * 16 + qrow;
        #pragma unroll
        for (int nb = 0; nb < 8; nb++) {
            const int col = o0 + nb * 8 + qcol;
            const float2 b2 = *(const float2*)&bv[col];
            float* d0 = &g_proj[((size_t)w * MM + r0) * DD + col];
            float* d1 = &g_proj[((size_t)w * MM + r0 + 8) * DD + col];
            ((float2*)d0)[0] = {acc[mt][nb][0] + b2.x, acc[mt][nb][1] + b2.y};
            ((float2*)d1)[0] = {acc[mt][nb][2] + b2.x, acc[mt][nb][3] + b2.y};
        }
    }
}

// ---------------------------------------------------------------------------
// attn: bucketed-moment temporal softmax
// NB=8 buckets, 2 warps per bucket (each scans half of D), ND=6 Taylor terms
// ---------------------------------------------------------------------------
__global__ __launch_bounds__(512) void attn_kernel(float* __restrict__ out) {
    const int m    = blockIdx.x;
    const int i    = threadIdx.x;
    const int lane = i & 31;
    const int wid  = i >> 5;     // 16 warps
    const float LOG2E = 1.4426950408889634f;

    const float* __restrict__ Qf = g_proj + (size_t)0 * MM * DD + (size_t)m * DD;
    const float* __restrict__ Kf = g_proj + (size_t)1 * MM * DD + (size_t)m * DD;
    const float* __restrict__ Vf = g_proj + (size_t)2 * MM * DD + (size_t)m * DD;
    const float* __restrict__ Qt = g_proj + (size_t)3 * MM * DD + (size_t)m * DD;
    const float* __restrict__ Kt = g_proj + (size_t)4 * MM * DD + (size_t)m * DD;
    const float* __restrict__ Vt = g_proj + (size_t)5 * MM * DD + (size_t)m * DD;

    __shared__ __align__(16) float sK[DD];
    __shared__ __align__(16) float sV[DD];
    __shared__ float sMA[NB][2][8];     // [bucket][half][moment], padded
    __shared__ float sMM[NB][2][8];
    __shared__ float redA[16], redB[16], redC[16];

    const float kt = Kt[i];
    sK[i] = kt;
    sV[i] = Vt[i];
    const float s  = Qf[i] * Kf[i];
    const float vf = Vf[i];
    const float c  = Qt[i];

    float smax = s, cmin = c, cmax = c;
    #pragma unroll
    for (int off = 16; off; off >>= 1) {
        smax = fmaxf(smax, __shfl_xor_sync(0xffffffffu, smax, off));
        cmin = fminf(cmin, __shfl_xor_sync(0xffffffffu, cmin, off));
        cmax = fmaxf(cmax, __shfl_xor_sync(0xffffffffu, cmax, off));
    }
    if (lane == 0) { redA[wid] = smax; redB[wid] = cmin; redC[wid] = cmax; }
    __syncthreads();   // also publishes sK / sV
    smax = redA[0]; cmin = redB[0]; cmax = redC[0];
    #pragma unroll
    for (int t = 1; t < 16; t++) {
        smax = fmaxf(smax, redA[t]);
        cmin = fminf(cmin, redB[t]);
        cmax = fmaxf(cmax, redC[t]);
    }
    __syncthreads();   // protect redA before reuse

    const float e = ex2f((s - smax) * LOG2E);
    float zf = e;
    #pragma unroll
    for (int off = 16; off; off >>= 1)
        zf += __shfl_xor_sync(0xffffffffu, zf, off);
    if (lane == 0) redA[wid] = zf;
    __syncthreads();
    zf = redA[0];
    #pragma unroll
    for (int t = 1; t < 16; t++) zf += redA[t];
    const float ctx_f = (e / zf) * vf;

    // ---- temporal phase 1: warp (bkt,half) scans j in [half*256, half*256+256)
    const int bkt  = wid >> 1;
    const int half = wid & 1;
    const float bw = (cmax - cmin) * (1.0f / NB);
    const float c0 = fmaf((float)bkt + 0.5f, bw, cmin);
    const float c0l = c0 * LOG2E;

    float a1[ND], m1[ND], a2[ND], m2[ND];
    #pragma unroll
    for (int n = 0; n < ND; n++) { a1[n] = 0.f; m1[n] = 0.f; a2[n] = 0.f; m2[n] = 0.f; }

    #pragma unroll
    for (int jj = 0; jj < 4; jj++) {
        const int j = half * 256 + jj * 64 + lane;
        const float ka = sK[j],      va = sV[j];
        const float kb = sK[j + 32], vb = sV[j + 32];
        float pa = ex2f(c0l * ka);
        float pb = ex2f(c0l * kb);
        #pragma unroll
        for (int n = 0; n < ND; n++) {
            a1[n] += pa;
            a2[n] += pb;
            m1[n]  = fmaf(pa, va, m1[n]);
            m2[n]  = fmaf(pb, vb, m2[n]);
            if (n < ND - 1) { pa *= ka; pb *= kb; }
        }
    }
    #pragma unroll
    for (int n = 0; n < ND; n++) {
        float av = a1[n] + a2[n], mv = m1[n] + m2[n];
        #pragma unroll
        for (int off = 16; off; off >>= 1) {
            av += __shfl_xor_sync(0xffffffffu, av, off);
            mv += __shfl_xor_sync(0xffffffffu, mv, off);
        }
        if (lane == 0) { sMA[bkt][half][n] = av; sMM[bkt][half][n] = mv; }
    }
    __syncthreads();

    // ---- temporal phase 2: per-thread Horner in d = c - c0_b ----
    const float W   = cmax - cmin;
    const float sc  = (W > 0.f) ? ((float)NB / W) : 0.f;
    int b = (int)((c - cmin) * sc);
    b = (b > NB - 1) ? NB - 1 : ((b < 0) ? 0 : b);
    const float d = c - fmaf((float)b + 0.5f, bw, cmin);

    const float IF[ND] = {1.f, 1.f, 0.5f, 1.f/6.f, 1.f/24.f, 1.f/120.f};
    const float* MA0 = sMA[b][0];
    const float* MA1 = sMA[b][1];
    const float* MM0 = sMM[b][0];
    const float* MM1 = sMM[b][1];
    float den = (MA0[ND - 1] + MA1[ND - 1]) * IF[ND - 1];
    float num = (MM0[ND - 1] + MM1[ND - 1]) * IF[ND - 1];
    #pragma unroll
    for (int n = ND - 2; n >= 0; n--) {
        den = fmaf(den, d, (MA0[n] + MA1[n]) * IF[n]);
        num = fmaf(num, d, (MM0[n] + MM1[n]) * IF[n]);
    }

    out[(size_t)m * DD + i] = ctx_f + num / den;
}

extern "C" void kernel_launch(void* const* d_in, const int* in_sizes, int n_in,
                              void* d_out, int out_size) {
    (void)in_sizes; (void)n_in; (void)out_size;
    const float* x = (const float*)d_in[0];
    WPtrs p;
    for (int w = 0; w < NWT; w++) {
        p.W[w] = (const float*)d_in[1 + 2 * w];
        p.b[w] = (const float*)d_in[2 + 2 * w];
    }
    cudaFuncSetAttribute(gemm_mma, cudaFuncAttributeMaxDynamicSharedMemorySize, GSMEM);
    conv_all<<<512, 256>>>(x, p);
    gemm_mma<<<dim3(MM / MT, NN / NT), 256, GSMEM>>>(p);
    attn_kernel<<<MM, 512>>>((float*)d_out);
}

// round 8
// speedup vs baseline: 2.4487x; 1.2023x over previous
#include <cuda_runtime.h>
#include <cuda_fp16.h>
#include <cstdint>

#define BB 8
#define TT 128
#define DD 512
#define MM (BB*TT)          // 1024 tokens
#define NWT 6
#define NN (NWT*DD)         // 3072 total output cols
#define KP2 1024            // A' = [x_hi | x_lo] (fp16)
#define KC 64
#define NCH (KP2/KC)        // 16 chunks
#define MT 128
#define NT 128
#define NSTG 3
#define STG_BYTES 32768     // A 16KB + B 16KB per stage
#define GSMEM (NSTG*STG_BYTES)
#define NB 8                // temporal buckets (2 warps per bucket)
#define ND 6                // Taylor terms (degree 5)

__device__ float g_proj[NWT * MM * DD];
__device__ __half gA[(size_t)MM * KP2];          // 2 MB  [xh | xl]
__device__ __half gB[(size_t)NN * DD];           // 3 MB  [wh] (read twice per K')

struct WPtrs { const float* W[NWT]; const float* b[NWT]; };

// ---------------------------------------------------------------------------
__device__ __forceinline__ uint32_t smem_u32(const void* p) {
    uint32_t a;
    asm("{ .reg .u64 t; cvta.to.shared.u64 t, %1; cvt.u32.u64 %0, t; }" : "=r"(a) : "l"(p));
    return a;
}
__device__ __forceinline__ void cp16(uint32_t saddr, const void* g) {
    asm volatile("cp.async.cg.shared.global [%0], [%1], 16;" :: "r"(saddr), "l"(g));
}
__device__ __forceinline__ void cp_commit() { asm volatile("cp.async.commit_group;" ::: "memory"); }
__device__ __forceinline__ void cp_wait1()  { asm volatile("cp.async.wait_group 1;" ::: "memory"); }
__device__ __forceinline__ void ldsm4(uint32_t* d, uint32_t a) {
    asm volatile("ldmatrix.sync.aligned.m8n8.x4.shared.b16 {%0,%1,%2,%3}, [%4];"
        : "=r"(d[0]), "=r"(d[1]), "=r"(d[2]), "=r"(d[3]) : "r"(a));
}
__device__ __forceinline__ void mma16816(float* c, const uint32_t* a, uint32_t b0, uint32_t b1) {
    asm volatile(
        "mma.sync.aligned.m16n8k16.row.col.f32.f16.f16.f32 "
        "{%0,%1,%2,%3}, {%4,%5,%6,%7}, {%8,%9}, {%0,%1,%2,%3};"
        : "+f"(c[0]), "+f"(c[1]), "+f"(c[2]), "+f"(c[3])
        : "r"(a[0]), "r"(a[1]), "r"(a[2]), "r"(a[3]), "r"(b0), "r"(b1));
}
__device__ __forceinline__ float ex2f(float x) { float y; asm("ex2.approx.f32 %0, %1;" : "=f"(y) : "f"(x)); return y; }

#define SW128(o) ((o) ^ (((o) >> 3) & 0x70))

// ---------------------------------------------------------------------------
// conv: fp32 -> fp16 hi/lo (x) and fp16 hi (W); 8 floats/thread, STG.128 only
//   blocks [0,256):   x  -> gA  (hi at col k, lo at col 512+k)
//   blocks [256,1024): W  -> gB  (hi only)
// ---------------------------------------------------------------------------
__device__ __forceinline__ uint4 pack8h(const __half* h) {
    uint4 u;
    u.x = (uint32_t)__half_as_ushort(h[0]) | ((uint32_t)__half_as_ushort(h[1]) << 16);
    u.y = (uint32_t)__half_as_ushort(h[2]) | ((uint32_t)__half_as_ushort(h[3]) << 16);
    u.z = (uint32_t)__half_as_ushort(h[4]) | ((uint32_t)__half_as_ushort(h[5]) << 16);
    u.w = (uint32_t)__half_as_ushort(h[6]) | ((uint32_t)__half_as_ushort(h[7]) << 16);
    return u;
}

__global__ __launch_bounds__(256) void conv_all(const float* __restrict__ x, WPtrs p) {
    const int blk = blockIdx.x;
    const int tid = threadIdx.x;
    if (blk < 256) {                      // ---- x path: 65536 chunks of 8 floats
        const int chunk = blk * 256 + tid;
        const int m  = chunk >> 6;
        const int k8 = (chunk & 63) << 3;
        const float4 v0 = *(const float4*)&x[(size_t)m * DD + k8];
        const float4 v1 = *(const float4*)&x[(size_t)m * DD + k8 + 4];
        const float vv[8] = {v0.x, v0.y, v0.z, v0.w, v1.x, v1.y, v1.z, v1.w};
        __half h[8], l[8];
        #pragma unroll
        for (int q = 0; q < 8; q++) {
            h[q] = __float2half_rn(vv[q]);
            l[q] = __float2half_rn(vv[q] - __half2float(h[q]));
        }
        *(uint4*)&gA[(size_t)m * KP2 + k8]       = pack8h(h);
        *(uint4*)&gA[(size_t)m * KP2 + 512 + k8] = pack8h(l);
    } else {                              // ---- W path: 196608 chunks
        const int t   = (blk - 256) * 256 + tid;
        const int w   = t >> 15;                 // 32768 chunks per matrix
        const int rem = t & 32767;
        const int o   = rem >> 6;
        const int k8  = (rem & 63) << 3;
        const float4 v0 = *(const float4*)&p.W[w][(size_t)o * DD + k8];
        const float4 v1 = *(const float4*)&p.W[w][(size_t)o * DD + k8 + 4];
        const float vv[8] = {v0.x, v0.y, v0.z, v0.w, v1.x, v1.y, v1.z, v1.w};
        __half h[8];
        #pragma unroll
        for (int q = 0; q < 8; q++) h[q] = __float2half_rn(vv[q]);
        *(uint4*)&gB[((size_t)w * DD + o) * DD + k8] = pack8h(h);
    }
}

// ---------------------------------------------------------------------------
// mma.sync fp16 GEMM: D[1024,3072] = [xh|xl] @ [wh|wh]^T + bias  (K'=1024)
// 3-stage cp.async pipeline, one __syncthreads per k-chunk.
// B chunks 8..15 re-read chunks 0..7 of gB (kb & 511) -> L2 hits.
// ---------------------------------------------------------------------------
__device__ __forceinline__ void load_chunk(int tid, int m0, int ng, int c, uint32_t stg) {
    const int kbA = c * KC;
    const int kbB = kbA & 511;
    const uint32_t sAb = stg, sBb = stg + 16384u;
    #pragma unroll
    for (int t = 0; t < 4; t++) {
        int idx = tid + t * 256;
        int row = idx >> 3, c16 = idx & 7;
        const char* ga = (const char*)gA + ((size_t)(m0 + row) * KP2 + kbA) * 2 + c16 * 16;
        cp16(sAb + SW128(row * 128 + c16 * 16), ga);
    }
    #pragma unroll
    for (int t = 0; t < 4; t++) {
        int idx = tid + t * 256;
        int row = idx >> 3, c16 = idx & 7;
        const char* gb = (const char*)gB + ((size_t)(ng + row) * DD + kbB) * 2 + c16 * 16;
        cp16(sBb + SW128(row * 128 + c16 * 16), gb);
    }
    cp_commit();
}

__global__ __launch_bounds__(256, 2) void gemm_mma(WPtrs p) {
    extern __shared__ __align__(1024) char dsm[];
    const uint32_t sbase = smem_u32(dsm);

    const int tid  = threadIdx.x;
    const int wid  = tid >> 5, lane = tid & 31;
    const int wm   = wid & 3;
    const int wn   = wid >> 2;
    const int m0 = blockIdx.x * MT;
    const int ng = blockIdx.y * NT;

    float acc[2][8][4];
    #pragma unroll
    for (int i = 0; i < 2; i++)
        #pragma unroll
        for (int j = 0; j < 8; j++)
            #pragma unroll
            for (int q = 0; q < 4; q++) acc[i][j][q] = 0.f;

    load_chunk(tid, m0, ng, 0, sbase);
    load_chunk(tid, m0, ng, 1, sbase + STG_BYTES);

    const int a_row  = wm * 32 + (lane & 15);
    const int a_koff = ((lane >> 4) << 3) * 2;
    const int b_row  = wn * 64 + (lane & 7) + ((lane >> 4) << 3);
    const int b_koff = (((lane >> 3) & 1) << 3) * 2;

    int slot = 0;
    int nslot = 2;
    for (int ch = 0; ch < NCH; ch++) {
        cp_wait1();
        __syncthreads();

        if (ch + 2 < NCH) load_chunk(tid, m0, ng, ch + 2, sbase + nslot * STG_BYTES);
        else cp_commit();

        const uint32_t sAb = sbase + slot * STG_BYTES;
        const uint32_t sBb = sAb + 16384u;
        #pragma unroll
        for (int ks = 0; ks < 4; ks++) {
            const int kb = ks * 32;
            uint32_t a[2][4];
            #pragma unroll
            for (int mt = 0; mt < 2; mt++)
                ldsm4(a[mt], sAb + SW128((a_row + mt * 16) * 128 + kb + a_koff));
            uint32_t b[4][4];
            #pragma unroll
            for (int nt = 0; nt < 4; nt++)
                ldsm4(b[nt], sBb + SW128((b_row + nt * 16) * 128 + kb + b_koff));
            #pragma unroll
            for (int mt = 0; mt < 2; mt++)
                #pragma unroll
                for (int nb = 0; nb < 8; nb++)
                    mma16816(acc[mt][nb], a[mt], b[nb >> 1][(nb & 1) * 2], b[nb >> 1][(nb & 1) * 2 + 1]);
        }
        nslot = slot;
        slot = (slot == 2) ? 0 : slot + 1;
    }

    const int w  = ng >> 9;
    const int o0 = (ng & 511) + wn * 64;
    const float* __restrict__ bv = p.b[w];
    const int qrow = lane >> 2;
    const int qcol = (lane & 3) * 2;
    #pragma unroll
    for (int mt = 0; mt < 2; mt++) {
        const int r0 = m0 + wm * 32 + mt * 16 + qrow;
        #pragma unroll
        for (int nb = 0; nb < 8; nb++) {
            const int col = o0 + nb * 8 + qcol;
            const float2 b2 = *(const float2*)&bv[col];
            float* d0 = &g_proj[((size_t)w * MM + r0) * DD + col];
            float* d1 = &g_proj[((size_t)w * MM + r0 + 8) * DD + col];
            ((float2*)d0)[0] = {acc[mt][nb][0] + b2.x, acc[mt][nb][1] + b2.y};
            ((float2*)d1)[0] = {acc[mt][nb][2] + b2.x, acc[mt][nb][3] + b2.y};
        }
    }
}

// ---------------------------------------------------------------------------
// attn: bucketed-moment temporal softmax (unchanged from R7)
// ---------------------------------------------------------------------------
__global__ __launch_bounds__(512) void attn_kernel(float* __restrict__ out) {
    const int m    = blockIdx.x;
    const int i    = threadIdx.x;
    const int lane = i & 31;
    const int wid  = i >> 5;     // 16 warps
    const float LOG2E = 1.4426950408889634f;

    const float* __restrict__ Qf = g_proj + (size_t)0 * MM * DD + (size_t)m * DD;
    const float* __restrict__ Kf = g_proj + (size_t)1 * MM * DD + (size_t)m * DD;
    const float* __restrict__ Vf = g_proj + (size_t)2 * MM * DD + (size_t)m * DD;
    const float* __restrict__ Qt = g_proj + (size_t)3 * MM * DD + (size_t)m * DD;
    const float* __restrict__ Kt = g_proj + (size_t)4 * MM * DD + (size_t)m * DD;
    const float* __restrict__ Vt = g_proj + (size_t)5 * MM * DD + (size_t)m * DD;

    __shared__ __align__(16) float sK[DD];
    __shared__ __align__(16) float sV[DD];
    __shared__ float sMA[NB][2][8];
    __shared__ float sMM[NB][2][8];
    __shared__ float redA[16], redB[16], redC[16];

    const float kt = Kt[i];
    sK[i] = kt;
    sV[i] = Vt[i];
    const float s  = Qf[i] * Kf[i];
    const float vf = Vf[i];
    const float c  = Qt[i];

    float smax = s, cmin = c, cmax = c;
    #pragma unroll
    for (int off = 16; off; off >>= 1) {
        smax = fmaxf(smax, __shfl_xor_sync(0xffffffffu, smax, off));
        cmin = fminf(cmin, __shfl_xor_sync(0xffffffffu, cmin, off));
        cmax = fmaxf(cmax, __shfl_xor_sync(0xffffffffu, cmax, off));
    }
    if (lane == 0) { redA[wid] = smax; redB[wid] = cmin; redC[wid] = cmax; }
    __syncthreads();   // also publishes sK / sV
    smax = redA[0]; cmin = redB[0]; cmax = redC[0];
    #pragma unroll
    for (int t = 1; t < 16; t++) {
        smax = fmaxf(smax, redA[t]);
        cmin = fminf(cmin, redB[t]);
        cmax = fmaxf(cmax, redC[t]);
    }
    __syncthreads();   // protect redA before reuse

    const float e = ex2f((s - smax) * LOG2E);
    float zf = e;
    #pragma unroll
    for (int off = 16; off; off >>= 1)
        zf += __shfl_xor_sync(0xffffffffu, zf, off);
    if (lane == 0) redA[wid] = zf;
    __syncthreads();
    zf = redA[0];
    #pragma unroll
    for (int t = 1; t < 16; t++) zf += redA[t];
    const float ctx_f = (e / zf) * vf;

    const int bkt  = wid >> 1;
    const int half = wid & 1;
    const float bw = (cmax - cmin) * (1.0f / NB);
    const float c0 = fmaf((float)bkt + 0.5f, bw, cmin);
    const float c0l = c0 * LOG2E;

    float a1[ND], m1[ND], a2[ND], m2[ND];
    #pragma unroll
    for (int n = 0; n < ND; n++) { a1[n] = 0.f; m1[n] = 0.f; a2[n] = 0.f; m2[n] = 0.f; }

    #pragma unroll
    for (int jj = 0; jj < 4; jj++) {
        const int j = half * 256 + jj * 64 + lane;
        const float ka = sK[j],      va = sV[j];
        const float kb = sK[j + 32], vb = sV[j + 32];
        float pa = ex2f(c0l * ka);
        float pb = ex2f(c0l * kb);
        #pragma unroll
        for (int n = 0; n < ND; n++) {
            a1[n] += pa;
            a2[n] += pb;
            m1[n]  = fmaf(pa, va, m1[n]);
            m2[n]  = fmaf(pb, vb, m2[n]);
            if (n < ND - 1) { pa *= ka; pb *= kb; }
        }
    }
    #pragma unroll
    for (int n = 0; n < ND; n++) {
        float av = a1[n] + a2[n], mv = m1[n] + m2[n];
        #pragma unroll
        for (int off = 16; off; off >>= 1) {
            av += __shfl_xor_sync(0xffffffffu, av, off);
            mv += __shfl_xor_sync(0xffffffffu, mv, off);
        }
        if (lane == 0) { sMA[bkt][half][n] = av; sMM[bkt][half][n] = mv; }
    }
    __syncthreads();

    const float W   = cmax - cmin;
    const float sc  = (W > 0.f) ? ((float)NB / W) : 0.f;
    int b = (int)((c - cmin) * sc);
    b = (b > NB - 1) ? NB - 1 : ((b < 0) ? 0 : b);
    const float d = c - fmaf((float)b + 0.5f, bw, cmin);

    const float IF[ND] = {1.f, 1.f, 0.5f, 1.f/6.f, 1.f/24.f, 1.f/120.f};
    const float* MA0 = sMA[b][0];
    const float* MA1 = sMA[b][1];
    const float* MM0 = sMM[b][0];
    const float* MM1 = sMM[b][1];
    float den = (MA0[ND - 1] + MA1[ND - 1]) * IF[ND - 1];
    float num = (MM0[ND - 1] + MM1[ND - 1]) * IF[ND - 1];
    #pragma unroll
    for (int n = ND - 2; n >= 0; n--) {
        den = fmaf(den, d, (MA0[n] + MA1[n]) * IF[n]);
        num = fmaf(num, d, (MM0[n] + MM1[n]) * IF[n]);
    }

    out[(size_t)m * DD + i] = ctx_f + num / den;
}

extern "C" void kernel_launch(void* const* d_in, const int* in_sizes, int n_in,
                              void* d_out, int out_size) {
    (void)in_sizes; (void)n_in; (void)out_size;
    const float* x = (const float*)d_in[0];
    WPtrs p;
    for (int w = 0; w < NWT; w++) {
        p.W[w] = (const float*)d_in[1 + 2 * w];
        p.b[w] = (const float*)d_in[2 + 2 * w];
    }
    cudaFuncSetAttribute(gemm_mma, cudaFuncAttributeMaxDynamicSharedMemorySize, GSMEM);
    conv_all<<<1024, 256>>>(x, p);
    gemm_mma<<<dim3(MM / MT, NN / NT), 256, GSMEM>>>(p);
    attn_kernel<<<MM, 512>>>((float*)d_out);
}

// round 9
// speedup vs baseline: 2.7163x; 1.1093x over previous
#include <cuda_runtime.h>
#include <cuda_fp16.h>
#include <cstdint>

#define BB 8
#define TT 128
#define DD 512
#define MM (BB*TT)          // 1024 tokens
#define NWT 6
#define NN (NWT*DD)         // 3072 total output cols
#define KP2 1024            // A' = [x_hi | x_lo] (fp16)
#define KC 64
#define NCH (KP2/KC)        // 16 chunks
#define MT 128
#define NT 96               // 8x32 = 256 CTAs -> one full wave at 2 CTAs/SM
#define NSTG 3
#define STG_BYTES (16384+12288)   // A 16KB + B 12KB per stage
#define GSMEM (NSTG*STG_BYTES)
#define NB 8                // temporal buckets (2 warps per bucket)
#define ND 6                // Taylor terms (degree 5)

__device__ float g_proj[NWT * MM * DD];
__device__ __half gA[(size_t)MM * KP2];          // 2 MB  [xh | xl]
__device__ __half gB[(size_t)NN * DD];           // 3 MB  [wh] (read twice per K')

struct WPtrs { const float* W[NWT]; const float* b[NWT]; };

// ---------------------------------------------------------------------------
__device__ __forceinline__ uint32_t smem_u32(const void* p) {
    uint32_t a;
    asm("{ .reg .u64 t; cvta.to.shared.u64 t, %1; cvt.u32.u64 %0, t; }" : "=r"(a) : "l"(p));
    return a;
}
__device__ __forceinline__ void cp16(uint32_t saddr, const void* g) {
    asm volatile("cp.async.cg.shared.global [%0], [%1], 16;" :: "r"(saddr), "l"(g));
}
__device__ __forceinline__ void cp_commit() { asm volatile("cp.async.commit_group;" ::: "memory"); }
__device__ __forceinline__ void cp_wait1()  { asm volatile("cp.async.wait_group 1;" ::: "memory"); }
__device__ __forceinline__ void ldsm4(uint32_t* d, uint32_t a) {
    asm volatile("ldmatrix.sync.aligned.m8n8.x4.shared.b16 {%0,%1,%2,%3}, [%4];"
        : "=r"(d[0]), "=r"(d[1]), "=r"(d[2]), "=r"(d[3]) : "r"(a));
}
__device__ __forceinline__ void mma16816(float* c, const uint32_t* a, uint32_t b0, uint32_t b1) {
    asm volatile(
        "mma.sync.aligned.m16n8k16.row.col.f32.f16.f16.f32 "
        "{%0,%1,%2,%3}, {%4,%5,%6,%7}, {%8,%9}, {%0,%1,%2,%3};"
        : "+f"(c[0]), "+f"(c[1]), "+f"(c[2]), "+f"(c[3])
        : "r"(a[0]), "r"(a[1]), "r"(a[2]), "r"(a[3]), "r"(b0), "r"(b1));
}
__device__ __forceinline__ float ex2f(float x) { float y; asm("ex2.approx.f32 %0, %1;" : "=f"(y) : "f"(x)); return y; }

#define SW128(o) ((o) ^ (((o) >> 3) & 0x70))

// ---------------------------------------------------------------------------
// conv: fp32 -> fp16 hi/lo (x) and fp16 hi (W); 8 floats/thread, STG.128 only
// ---------------------------------------------------------------------------
__device__ __forceinline__ uint4 pack8h(const __half* h) {
    uint4 u;
    u.x = (uint32_t)__half_as_ushort(h[0]) | ((uint32_t)__half_as_ushort(h[1]) << 16);
    u.y = (uint32_t)__half_as_ushort(h[2]) | ((uint32_t)__half_as_ushort(h[3]) << 16);
    u.z = (uint32_t)__half_as_ushort(h[4]) | ((uint32_t)__half_as_ushort(h[5]) << 16);
    u.w = (uint32_t)__half_as_ushort(h[6]) | ((uint32_t)__half_as_ushort(h[7]) << 16);
    return u;
}

__global__ __launch_bounds__(256) void conv_all(const float* __restrict__ x, WPtrs p) {
    const int blk = blockIdx.x;
    const int tid = threadIdx.x;
    if (blk < 256) {                      // ---- x path
        const int chunk = blk * 256 + tid;
        const int m  = chunk >> 6;
        const int k8 = (chunk & 63) << 3;
        const float4 v0 = *(const float4*)&x[(size_t)m * DD + k8];
        const float4 v1 = *(const float4*)&x[(size_t)m * DD + k8 + 4];
        const float vv[8] = {v0.x, v0.y, v0.z, v0.w, v1.x, v1.y, v1.z, v1.w};
        __half h[8], l[8];
        #pragma unroll
        for (int q = 0; q < 8; q++) {
            h[q] = __float2half_rn(vv[q]);
            l[q] = __float2half_rn(vv[q] - __half2float(h[q]));
        }
        *(uint4*)&gA[(size_t)m * KP2 + k8]       = pack8h(h);
        *(uint4*)&gA[(size_t)m * KP2 + 512 + k8] = pack8h(l);
    } else {                              // ---- W path
        const int t   = (blk - 256) * 256 + tid;
        const int w   = t >> 15;
        const int rem = t & 32767;
        const int o   = rem >> 6;
        const int k8  = (rem & 63) << 3;
        const float4 v0 = *(const float4*)&p.W[w][(size_t)o * DD + k8];
        const float4 v1 = *(const float4*)&p.W[w][(size_t)o * DD + k8 + 4];
        const float vv[8] = {v0.x, v0.y, v0.z, v0.w, v1.x, v1.y, v1.z, v1.w};
        __half h[8];
        #pragma unroll
        for (int q = 0; q < 8; q++) h[q] = __float2half_rn(vv[q]);
        *(uint4*)&gB[((size_t)w * DD + o) * DD + k8] = pack8h(h);
    }
}

// ---------------------------------------------------------------------------
// mma.sync fp16 GEMM: D[1024,3072] = [xh|xl] @ [wh|wh]^T + bias  (K'=1024)
// CTA tile 128x96, 3-stage cp.async pipeline, 256 CTAs = one wave.
// ---------------------------------------------------------------------------
__device__ __forceinline__ void load_chunk(int tid, int m0, int ng, int c, uint32_t stg) {
    const int kbA = c * KC;
    const int kbB = kbA & 511;
    const uint32_t sAb = stg, sBb = stg + 16384u;
    #pragma unroll
    for (int t = 0; t < 4; t++) {
        int idx = tid + t * 256;
        int row = idx >> 3, c16 = idx & 7;
        const char* ga = (const char*)gA + ((size_t)(m0 + row) * KP2 + kbA) * 2 + c16 * 16;
        cp16(sAb + SW128(row * 128 + c16 * 16), ga);
    }
    #pragma unroll
    for (int t = 0; t < 3; t++) {         // 96 rows x 8 groups = 768
        int idx = tid + t * 256;
        int row = idx >> 3, c16 = idx & 7;
        const char* gb = (const char*)gB + ((size_t)(ng + row) * DD + kbB) * 2 + c16 * 16;
        cp16(sBb + SW128(row * 128 + c16 * 16), gb);
    }
    cp_commit();
}

__global__ __launch_bounds__(256, 2) void gemm_mma(WPtrs p) {
    extern __shared__ __align__(1024) char dsm[];
    const uint32_t sbase = smem_u32(dsm);

    const int tid  = threadIdx.x;
    const int wid  = tid >> 5, lane = tid & 31;
    const int wm   = wid & 3;        // m offset = wm*32
    const int wn   = wid >> 2;       // n offset = wn*48
    const int m0 = blockIdx.x * MT;
    const int ng = blockIdx.y * NT;

    float acc[2][6][4];
    #pragma unroll
    for (int i = 0; i < 2; i++)
        #pragma unroll
        for (int j = 0; j < 6; j++)
            #pragma unroll
            for (int q = 0; q < 4; q++) acc[i][j][q] = 0.f;

    load_chunk(tid, m0, ng, 0, sbase);
    load_chunk(tid, m0, ng, 1, sbase + STG_BYTES);

    const int a_row  = wm * 32 + (lane & 15);
    const int a_koff = ((lane >> 4) << 3) * 2;
    const int b_row  = wn * 48 + (lane & 7) + ((lane >> 4) << 3);
    const int b_koff = (((lane >> 3) & 1) << 3) * 2;

    int slot = 0;
    int nslot = 2;
    for (int ch = 0; ch < NCH; ch++) {
        cp_wait1();
        __syncthreads();

        if (ch + 2 < NCH) load_chunk(tid, m0, ng, ch + 2, sbase + nslot * STG_BYTES);
        else cp_commit();

        const uint32_t sAb = sbase + slot * STG_BYTES;
        const uint32_t sBb = sAb + 16384u;
        #pragma unroll
        for (int ks = 0; ks < 4; ks++) {
            const int kb = ks * 32;
            uint32_t a[2][4];
            #pragma unroll
            for (int mt = 0; mt < 2; mt++)
                ldsm4(a[mt], sAb + SW128((a_row + mt * 16) * 128 + kb + a_koff));
            uint32_t b[3][4];
            #pragma unroll
            for (int nt = 0; nt < 3; nt++)
                ldsm4(b[nt], sBb + SW128((b_row + nt * 16) * 128 + kb + b_koff));
            #pragma unroll
            for (int mt = 0; mt < 2; mt++)
                #pragma unroll
                for (int nb = 0; nb < 6; nb++)
                    mma16816(acc[mt][nb], a[mt], b[nb >> 1][(nb & 1) * 2], b[nb >> 1][(nb & 1) * 2 + 1]);
        }
        nslot = slot;
        slot = (slot == 2) ? 0 : slot + 1;
    }

    // epilogue: + bias, write fp32 projections (tile may span W matrices)
    const int qrow = lane >> 2;
    const int qcol = (lane & 3) * 2;
    #pragma unroll
    for (int mt = 0; mt < 2; mt++) {
        const int r0 = m0 + wm * 32 + mt * 16 + qrow;
        #pragma unroll
        for (int nb = 0; nb < 6; nb++) {
            const int n  = ng + wn * 48 + nb * 8 + qcol;   // global col in [0,3072)
            const int nw = n >> 9;
            const int no = n & 511;
            const float2 b2 = *(const float2*)&p.b[nw][no];
            float* d0 = &g_proj[((size_t)nw * MM + r0) * DD + no];
            float* d1 = &g_proj[((size_t)nw * MM + r0 + 8) * DD + no];
            ((float2*)d0)[0] = {acc[mt][nb][0] + b2.x, acc[mt][nb][1] + b2.y};
            ((float2*)d1)[0] = {acc[mt][nb][2] + b2.x, acc[mt][nb][3] + b2.y};
        }
    }
}

// ---------------------------------------------------------------------------
// attn: bucketed-moment temporal softmax (unchanged)
// ---------------------------------------------------------------------------
__global__ __launch_bounds__(512) void attn_kernel(float* __restrict__ out) {
    const int m    = blockIdx.x;
    const int i    = threadIdx.x;
    const int lane = i & 31;
    const int wid  = i >> 5;
    const float LOG2E = 1.4426950408889634f;

    const float* __restrict__ Qf = g_proj + (size_t)0 * MM * DD + (size_t)m * DD;
    const float* __restrict__ Kf = g_proj + (size_t)1 * MM * DD + (size_t)m * DD;
    const float* __restrict__ Vf = g_proj + (size_t)2 * MM * DD + (size_t)m * DD;
    const float* __restrict__ Qt = g_proj + (size_t)3 * MM * DD + (size_t)m * DD;
    const float* __restrict__ Kt = g_proj + (size_t)4 * MM * DD + (size_t)m * DD;
    const float* __restrict__ Vt = g_proj + (size_t)5 * MM * DD + (size_t)m * DD;

    __shared__ __align__(16) float sK[DD];
    __shared__ __align__(16) float sV[DD];
    __shared__ float sMA[NB][2][8];
    __shared__ float sMM[NB][2][8];
    __shared__ float redA[16], redB[16], redC[16];

    const float kt = Kt[i];
    sK[i] = kt;
    sV[i] = Vt[i];
    const float s  = Qf[i] * Kf[i];
    const float vf = Vf[i];
    const float c  = Qt[i];

    float smax = s, cmin = c, cmax = c;
    #pragma unroll
    for (int off = 16; off; off >>= 1) {
        smax = fmaxf(smax, __shfl_xor_sync(0xffffffffu, smax, off));
        cmin = fminf(cmin, __shfl_xor_sync(0xffffffffu, cmin, off));
        cmax = fmaxf(cmax, __shfl_xor_sync(0xffffffffu, cmax, off));
    }
    if (lane == 0) { redA[wid] = smax; redB[wid] = cmin; redC[wid] = cmax; }
    __syncthreads();
    smax = redA[0]; cmin = redB[0]; cmax = redC[0];
    #pragma unroll
    for (int t = 1; t < 16; t++) {
        smax = fmaxf(smax, redA[t]);
        cmin = fminf(cmin, redB[t]);
        cmax = fmaxf(cmax, redC[t]);
    }
    __syncthreads();

    const float e = ex2f((s - smax) * LOG2E);
    float zf = e;
    #pragma unroll
    for (int off = 16; off; off >>= 1)
        zf += __shfl_xor_sync(0xffffffffu, zf, off);
    if (lane == 0) redA[wid] = zf;
    __syncthreads();
    zf = redA[0];
    #pragma unroll
    for (int t = 1; t < 16; t++) zf += redA[t];
    const float ctx_f = (e / zf) * vf;

    const int bkt  = wid >> 1;
    const int half = wid & 1;
    const float bw = (cmax - cmin) * (1.0f / NB);
    const float c0 = fmaf((float)bkt + 0.5f, bw, cmin);
    const float c0l = c0 * LOG2E;

    float a1[ND], m1[ND], a2[ND], m2[ND];
    #pragma unroll
    for (int n = 0; n < ND; n++) { a1[n] = 0.f; m1[n] = 0.f; a2[n] = 0.f; m2[n] = 0.f; }

    #pragma unroll
    for (int jj = 0; jj < 4; jj++) {
        const int j = half * 256 + jj * 64 + lane;
        const float ka = sK[j],      va = sV[j];
        const float kb = sK[j + 32], vb = sV[j + 32];
        float pa = ex2f(c0l * ka);
        float pb = ex2f(c0l * kb);
        #pragma unroll
        for (int n = 0; n < ND; n++) {
            a1[n] += pa;
            a2[n] += pb;
            m1[n]  = fmaf(pa, va, m1[n]);
            m2[n]  = fmaf(pb, vb, m2[n]);
            if (n < ND - 1) { pa *= ka; pb *= kb; }
        }
    }
    #pragma unroll
    for (int n = 0; n < ND; n++) {
        float av = a1[n] + a2[n], mv = m1[n] + m2[n];
        #pragma unroll
        for (int off = 16; off; off >>= 1) {
            av += __shfl_xor_sync(0xffffffffu, av, off);
            mv += __shfl_xor_sync(0xffffffffu, mv, off);
        }
        if (lane == 0) { sMA[bkt][half][n] = av; sMM[bkt][half][n] = mv; }
    }
    __syncthreads();

    const float W   = cmax - cmin;
    const float sc  = (W > 0.f) ? ((float)NB / W) : 0.f;
    int b = (int)((c - cmin) * sc);
    b = (b > NB - 1) ? NB - 1 : ((b < 0) ? 0 : b);
    const float d = c - fmaf((float)b + 0.5f, bw, cmin);

    const float IF[ND] = {1.f, 1.f, 0.5f, 1.f/6.f, 1.f/24.f, 1.f/120.f};
    const float* MA0 = sMA[b][0];
    const float* MA1 = sMA[b][1];
    const float* MM0 = sMM[b][0];
    const float* MM1 = sMM[b][1];
    float den = (MA0[ND - 1] + MA1[ND - 1]) * IF[ND - 1];
    float num = (MM0[ND - 1] + MM1[ND - 1]) * IF[ND - 1];
    #pragma unroll
    for (int n = ND - 2; n >= 0; n--) {
        den = fmaf(den, d, (MA0[n] + MA1[n]) * IF[n]);
        num = fmaf(num, d, (MM0[n] + MM1[n]) * IF[n]);
    }

    out[(size_t)m * DD + i] = ctx_f + num / den;
}

extern "C" void kernel_launch(void* const* d_in, const int* in_sizes, int n_in,
                              void* d_out, int out_size) {
    (void)in_sizes; (void)n_in; (void)out_size;
    const float* x = (const float*)d_in[0];
    WPtrs p;
    for (int w = 0; w < NWT; w++) {
        p.W[w] = (const float*)d_in[1 + 2 * w];
        p.b[w] = (const float*)d_in[2 + 2 * w];
    }
    cudaFuncSetAttribute(gemm_mma, cudaFuncAttributeMaxDynamicSharedMemorySize, GSMEM);
    conv_all<<<1024, 256>>>(x, p);
    gemm_mma<<<dim3(MM / MT, NN / NT), 256, GSMEM>>>(p);
    attn_kernel<<<MM, 512>>>((float*)d_out);
}

// round 10
// speedup vs baseline: 3.2694x; 1.2036x over previous
#include <cuda_runtime.h>
#include <cuda_fp16.h>
#include <cstdint>

#define BB 8
#define TT 128
#define DD 512
#define MM (BB*TT)          // 1024 tokens
#define NWT 6
#define NN (NWT*DD)         // 3072 total output cols
#define KC 64
#define NCH (DD/KC)         // 8 chunks (pure fp16, K'=512)
#define MT 128
#define NT 96               // 8x32 = 256 CTAs -> one full wave at 2 CTAs/SM
#define NSTG 3
#define STG_BYTES (16384+12288)   // A 16KB + B 12KB per stage
#define GSMEM (NSTG*STG_BYTES)
#define NB 8                // temporal buckets (2 warps per bucket)
#define ND 6                // Taylor terms (degree 5)

__device__ float g_proj[NWT * MM * DD];
__device__ __half gA[(size_t)MM * DD];           // 1 MB  xh
__device__ __half gB[(size_t)NN * DD];           // 3 MB  wh

struct WPtrs { const float* W[NWT]; const float* b[NWT]; };

// ---------------------------------------------------------------------------
__device__ __forceinline__ uint32_t smem_u32(const void* p) {
    uint32_t a;
    asm("{ .reg .u64 t; cvta.to.shared.u64 t, %1; cvt.u32.u64 %0, t; }" : "=r"(a) : "l"(p));
    return a;
}
__device__ __forceinline__ void cp16(uint32_t saddr, const void* g) {
    asm volatile("cp.async.cg.shared.global [%0], [%1], 16;" :: "r"(saddr), "l"(g));
}
__device__ __forceinline__ void cp_commit() { asm volatile("cp.async.commit_group;" ::: "memory"); }
__device__ __forceinline__ void cp_wait1()  { asm volatile("cp.async.wait_group 1;" ::: "memory"); }
__device__ __forceinline__ void ldsm4(uint32_t* d, uint32_t a) {
    asm volatile("ldmatrix.sync.aligned.m8n8.x4.shared.b16 {%0,%1,%2,%3}, [%4];"
        : "=r"(d[0]), "=r"(d[1]), "=r"(d[2]), "=r"(d[3]) : "r"(a));
}
__device__ __forceinline__ void mma16816(float* c, const uint32_t* a, uint32_t b0, uint32_t b1) {
    asm volatile(
        "mma.sync.aligned.m16n8k16.row.col.f32.f16.f16.f32 "
        "{%0,%1,%2,%3}, {%4,%5,%6,%7}, {%8,%9}, {%0,%1,%2,%3};"
        : "+f"(c[0]), "+f"(c[1]), "+f"(c[2]), "+f"(c[3])
        : "r"(a[0]), "r"(a[1]), "r"(a[2]), "r"(a[3]), "r"(b0), "r"(b1));
}
__device__ __forceinline__ float ex2f(float x) { float y; asm("ex2.approx.f32 %0, %1;" : "=f"(y) : "f"(x)); return y; }

#define SW128(o) ((o) ^ (((o) >> 3) & 0x70))

// ---------------------------------------------------------------------------
// conv: fp32 -> fp16 (single rounding, both x and W); 8 floats/thread
// ---------------------------------------------------------------------------
__device__ __forceinline__ uint4 pack8h(const __half* h) {
    uint4 u;
    u.x = (uint32_t)__half_as_ushort(h[0]) | ((uint32_t)__half_as_ushort(h[1]) << 16);
    u.y = (uint32_t)__half_as_ushort(h[2]) | ((uint32_t)__half_as_ushort(h[3]) << 16);
    u.z = (uint32_t)__half_as_ushort(h[4]) | ((uint32_t)__half_as_ushort(h[5]) << 16);
    u.w = (uint32_t)__half_as_ushort(h[6]) | ((uint32_t)__half_as_ushort(h[7]) << 16);
    return u;
}

__global__ __launch_bounds__(256) void conv_all(const float* __restrict__ x, WPtrs p) {
    const int blk = blockIdx.x;
    const int tid = threadIdx.x;
    if (blk < 256) {                      // ---- x path: 65536 chunks of 8
        const int chunk = blk * 256 + tid;
        const int m  = chunk >> 6;
        const int k8 = (chunk & 63) << 3;
        const float4 v0 = *(const float4*)&x[(size_t)m * DD + k8];
        const float4 v1 = *(const float4*)&x[(size_t)m * DD + k8 + 4];
        const float vv[8] = {v0.x, v0.y, v0.z, v0.w, v1.x, v1.y, v1.z, v1.w};
        __half h[8];
        #pragma unroll
        for (int q = 0; q < 8; q++) h[q] = __float2half_rn(vv[q]);
        *(uint4*)&gA[(size_t)m * DD + k8] = pack8h(h);
    } else {                              // ---- W path: 196608 chunks
        const int t   = (blk - 256) * 256 + tid;
        const int w   = t >> 15;
        const int rem = t & 32767;
        const int o   = rem >> 6;
        const int k8  = (rem & 63) << 3;
        const float4 v0 = *(const float4*)&p.W[w][(size_t)o * DD + k8];
        const float4 v1 = *(const float4*)&p.W[w][(size_t)o * DD + k8 + 4];
        const float vv[8] = {v0.x, v0.y, v0.z, v0.w, v1.x, v1.y, v1.z, v1.w};
        __half h[8];
        #pragma unroll
        for (int q = 0; q < 8; q++) h[q] = __float2half_rn(vv[q]);
        *(uint4*)&gB[((size_t)w * DD + o) * DD + k8] = pack8h(h);
    }
}

// ---------------------------------------------------------------------------
// mma.sync fp16 GEMM: D[1024,3072] = xh @ wh^T + bias  (K=512, 8 chunks)
// CTA tile 128x96, 3-stage cp.async pipeline, 256 CTAs = one wave.
// ---------------------------------------------------------------------------
__device__ __forceinline__ void load_chunk(int tid, int m0, int ng, int c, uint32_t stg) {
    const int kb = c * KC;
    const uint32_t sAb = stg, sBb = stg + 16384u;
    #pragma unroll
    for (int t = 0; t < 4; t++) {
        int idx = tid + t * 256;
        int row = idx >> 3, c16 = idx & 7;
        const char* ga = (const char*)gA + ((size_t)(m0 + row) * DD + kb) * 2 + c16 * 16;
        cp16(sAb + SW128(row * 128 + c16 * 16), ga);
    }
    #pragma unroll
    for (int t = 0; t < 3; t++) {         // 96 rows x 8 groups = 768
        int idx = tid + t * 256;
        int row = idx >> 3, c16 = idx & 7;
        const char* gb = (const char*)gB + ((size_t)(ng + row) * DD + kb) * 2 + c16 * 16;
        cp16(sBb + SW128(row * 128 + c16 * 16), gb);
    }
    cp_commit();
}

__global__ __launch_bounds__(256, 2) void gemm_mma(WPtrs p) {
    extern __shared__ __align__(1024) char dsm[];
    const uint32_t sbase = smem_u32(dsm);

    const int tid  = threadIdx.x;
    const int wid  = tid >> 5, lane = tid & 31;
    const int wm   = wid & 3;        // m offset = wm*32
    const int wn   = wid >> 2;       // n offset = wn*48
    const int m0 = blockIdx.x * MT;
    const int ng = blockIdx.y * NT;

    float acc[2][6][4];
    #pragma unroll
    for (int i = 0; i < 2; i++)
        #pragma unroll
        for (int j = 0; j < 6; j++)
            #pragma unroll
            for (int q = 0; q < 4; q++) acc[i][j][q] = 0.f;

    load_chunk(tid, m0, ng, 0, sbase);
    load_chunk(tid, m0, ng, 1, sbase + STG_BYTES);

    const int a_row  = wm * 32 + (lane & 15);
    const int a_koff = ((lane >> 4) << 3) * 2;
    const int b_row  = wn * 48 + (lane & 7) + ((lane >> 4) << 3);
    const int b_koff = (((lane >> 3) & 1) << 3) * 2;

    int slot = 0;
    int nslot = 2;
    for (int ch = 0; ch < NCH; ch++) {
        cp_wait1();
        __syncthreads();

        if (ch + 2 < NCH) load_chunk(tid, m0, ng, ch + 2, sbase + nslot * STG_BYTES);
        else cp_commit();

        const uint32_t sAb = sbase + slot * STG_BYTES;
        const uint32_t sBb = sAb + 16384u;
        #pragma unroll
        for (int ks = 0; ks < 4; ks++) {
            const int kb = ks * 32;
            uint32_t a[2][4];
            #pragma unroll
            for (int mt = 0; mt < 2; mt++)
                ldsm4(a[mt], sAb + SW128((a_row + mt * 16) * 128 + kb + a_koff));
            uint32_t b[3][4];
            #pragma unroll
            for (int nt = 0; nt < 3; nt++)
                ldsm4(b[nt], sBb + SW128((b_row + nt * 16) * 128 + kb + b_koff));
            #pragma unroll
            for (int mt = 0; mt < 2; mt++)
                #pragma unroll
                for (int nb = 0; nb < 6; nb++)
                    mma16816(acc[mt][nb], a[mt], b[nb >> 1][(nb & 1) * 2], b[nb >> 1][(nb & 1) * 2 + 1]);
        }
        nslot = slot;
        slot = (slot == 2) ? 0 : slot + 1;
    }

    // epilogue: + bias, write fp32 projections (tile may span W matrices)
    const int qrow = lane >> 2;
    const int qcol = (lane & 3) * 2;
    #pragma unroll
    for (int mt = 0; mt < 2; mt++) {
        const int r0 = m0 + wm * 32 + mt * 16 + qrow;
        #pragma unroll
        for (int nb = 0; nb < 6; nb++) {
            const int n  = ng + wn * 48 + nb * 8 + qcol;   // global col in [0,3072)
            const int nw = n >> 9;
            const int no = n & 511;
            const float2 b2 = *(const float2*)&p.b[nw][no];
            float* d0 = &g_proj[((size_t)nw * MM + r0) * DD + no];
            float* d1 = &g_proj[((size_t)nw * MM + r0 + 8) * DD + no];
            ((float2*)d0)[0] = {acc[mt][nb][0] + b2.x, acc[mt][nb][1] + b2.y};
            ((float2*)d1)[0] = {acc[mt][nb][2] + b2.x, acc[mt][nb][3] + b2.y};
        }
    }
}

// ---------------------------------------------------------------------------
// attn: bucketed-moment temporal softmax (unchanged)
// ---------------------------------------------------------------------------
__global__ __launch_bounds__(512) void attn_kernel(float* __restrict__ out) {
    const int m    = blockIdx.x;
    const int i    = threadIdx.x;
    const int lane = i & 31;
    const int wid  = i >> 5;
    const float LOG2E = 1.4426950408889634f;

    const float* __restrict__ Qf = g_proj + (size_t)0 * MM * DD + (size_t)m * DD;
    const float* __restrict__ Kf = g_proj + (size_t)1 * MM * DD + (size_t)m * DD;
    const float* __restrict__ Vf = g_proj + (size_t)2 * MM * DD + (size_t)m * DD;
    const float* __restrict__ Qt = g_proj + (size_t)3 * MM * DD + (size_t)m * DD;
    const float* __restrict__ Kt = g_proj + (size_t)4 * MM * DD + (size_t)m * DD;
    const float* __restrict__ Vt = g_proj + (size_t)5 * MM * DD + (size_t)m * DD;

    __shared__ __align__(16) float sK[DD];
    __shared__ __align__(16) float sV[DD];
    __shared__ float sMA[NB][2][8];
    __shared__ float sMM[NB][2][8];
    __shared__ float redA[16], redB[16], redC[16];

    const float kt = Kt[i];
    sK[i] = kt;
    sV[i] = Vt[i];
    const float s  = Qf[i] * Kf[i];
    const float vf = Vf[i];
    const float c  = Qt[i];

    float smax = s, cmin = c, cmax = c;
    #pragma unroll
    for (int off = 16; off; off >>= 1) {
        smax = fmaxf(smax, __shfl_xor_sync(0xffffffffu, smax, off));
        cmin = fminf(cmin, __shfl_xor_sync(0xffffffffu, cmin, off));
        cmax = fmaxf(cmax, __shfl_xor_sync(0xffffffffu, cmax, off));
    }
    if (lane == 0) { redA[wid] = smax; redB[wid] = cmin; redC[wid] = cmax; }
    __syncthreads();
    smax = redA[0]; cmin = redB[0]; cmax = redC[0];
    #pragma unroll
    for (int t = 1; t < 16; t++) {
        smax = fmaxf(smax, redA[t]);
        cmin = fminf(cmin, redB[t]);
        cmax = fmaxf(cmax, redC[t]);
    }
    __syncthreads();

    const float e = ex2f((s - smax) * LOG2E);
    float zf = e;
    #pragma unroll
    for (int off = 16; off; off >>= 1)
        zf += __shfl_xor_sync(0xffffffffu, zf, off);
    if (lane == 0) redA[wid] = zf;
    __syncthreads();
    zf = redA[0];
    #pragma unroll
    for (int t = 1; t < 16; t++) zf += redA[t];
    const float ctx_f = (e / zf) * vf;

    const int bkt  = wid >> 1;
    const int half = wid & 1;
    const float bw = (cmax - cmin) * (1.0f / NB);
    const float c0 = fmaf((float)bkt + 0.5f, bw, cmin);
    const float c0l = c0 * LOG2E;

    float a1[ND], m1[ND], a2[ND], m2[ND];
    #pragma unroll
    for (int n = 0; n < ND; n++) { a1[n] = 0.f; m1[n] = 0.f; a2[n] = 0.f; m2[n] = 0.f; }

    #pragma unroll
    for (int jj = 0; jj < 4; jj++) {
        const int j = half * 256 + jj * 64 + lane;
        const float ka = sK[j],      va = sV[j];
        const float kb = sK[j + 32], vb = sV[j + 32];
        float pa = ex2f(c0l * ka);
        float pb = ex2f(c0l * kb);
        #pragma unroll
        for (int n = 0; n < ND; n++) {
            a1[n] += pa;
            a2[n] += pb;
            m1[n]  = fmaf(pa, va, m1[n]);
            m2[n]  = fmaf(pb, vb, m2[n]);
            if (n < ND - 1) { pa *= ka; pb *= kb; }
        }
    }
    #pragma unroll
    for (int n = 0; n < ND; n++) {
        float av = a1[n] + a2[n], mv = m1[n] + m2[n];
        #pragma unroll
        for (int off = 16; off; off >>= 1) {
            av += __shfl_xor_sync(0xffffffffu, av, off);
            mv += __shfl_xor_sync(0xffffffffu, mv, off);
        }
        if (lane == 0) { sMA[bkt][half][n] = av; sMM[bkt][half][n] = mv; }
    }
    __syncthreads();

    const float W   = cmax - cmin;
    const float sc  = (W > 0.f) ? ((float)NB / W) : 0.f;
    int b = (int)((c - cmin) * sc);
    b = (b > NB - 1) ? NB - 1 : ((b < 0) ? 0 : b);
    const float d = c - fmaf((float)b + 0.5f, bw, cmin);

    const float IF[ND] = {1.f, 1.f, 0.5f, 1.f/6.f, 1.f/24.f, 1.f/120.f};
    const float* MA0 = sMA[b][0];
    const float* MA1 = sMA[b][1];
    const float* MM0 = sMM[b][0];
    const float* MM1 = sMM[b][1];
    float den = (MA0[ND - 1] + MA1[ND - 1]) * IF[ND - 1];
    float num = (MM0[ND - 1] + MM1[ND - 1]) * IF[ND - 1];
    #pragma unroll
    for (int n = ND - 2; n >= 0; n--) {
        den = fmaf(den, d, (MA0[n] + MA1[n]) * IF[n]);
        num = fmaf(num, d, (MM0[n] + MM1[n]) * IF[n]);
    }

    out[(size_t)m * DD + i] = ctx_f + num / den;
}

extern "C" void kernel_launch(void* const* d_in, const int* in_sizes, int n_in,
                              void* d_out, int out_size) {
    (void)in_sizes; (void)n_in; (void)out_size;
    const float* x = (const float*)d_in[0];
    WPtrs p;
    for (int w = 0; w < NWT; w++) {
        p.W[w] = (const float*)d_in[1 + 2 * w];
        p.b[w] = (const float*)d_in[2 + 2 * w];
    }
    cudaFuncSetAttribute(gemm_mma, cudaFuncAttributeMaxDynamicSharedMemorySize, GSMEM);
    conv_all<<<1024, 256>>>(x, p);
    gemm_mma<<<dim3(MM / MT, NN / NT), 256, GSMEM>>>(p);
    attn_kernel<<<MM, 512>>>((float*)d_out);
}

// round 11
// speedup vs baseline: 3.9838x; 1.2185x over previous
#include <cuda_runtime.h>
#include <cuda_fp16.h>
#include <cstdint>

#define BB 8
#define TT 128
#define DD 512
#define MM (BB*TT)          // 1024 tokens
#define NWT 6
#define NN (NWT*DD)         // 3072 total output cols
#define KC 64
#define NCH (DD/KC)         // 8 chunks (pure fp16, K=512)
#define MT 128
#define NT 96               // 8x32 = 256 CTAs -> one full wave at 2 CTAs/SM
#define NSTG 3
#define STG_BYTES (16384+12288)   // A 16KB + B 12KB per stage
#define GSMEM (NSTG*STG_BYTES)
#define NB 8                // temporal buckets == warps per CTA (attn)
#define ND 6                // Taylor terms (degree 5)

__device__ float g_proj[NWT * MM * DD];
__device__ __half gA[(size_t)MM * DD];           // 1 MB  xh
__device__ __half gB[(size_t)NN * DD];           // 3 MB  wh

struct WPtrs { const float* W[NWT]; const float* b[NWT]; };

// ---------------------------------------------------------------------------
__device__ __forceinline__ uint32_t smem_u32(const void* p) {
    uint32_t a;
    asm("{ .reg .u64 t; cvta.to.shared.u64 t, %1; cvt.u32.u64 %0, t; }" : "=r"(a) : "l"(p));
    return a;
}
__device__ __forceinline__ void cp16(uint32_t saddr, const void* g) {
    asm volatile("cp.async.cg.shared.global [%0], [%1], 16;" :: "r"(saddr), "l"(g));
}
__device__ __forceinline__ void cp_commit() { asm volatile("cp.async.commit_group;" ::: "memory"); }
__device__ __forceinline__ void cp_wait1()  { asm volatile("cp.async.wait_group 1;" ::: "memory"); }
__device__ __forceinline__ void ldsm4(uint32_t* d, uint32_t a) {
    asm volatile("ldmatrix.sync.aligned.m8n8.x4.shared.b16 {%0,%1,%2,%3}, [%4];"
        : "=r"(d[0]), "=r"(d[1]), "=r"(d[2]), "=r"(d[3]) : "r"(a));
}
__device__ __forceinline__ void mma16816(float* c, const uint32_t* a, uint32_t b0, uint32_t b1) {
    asm volatile(
        "mma.sync.aligned.m16n8k16.row.col.f32.f16.f16.f32 "
        "{%0,%1,%2,%3}, {%4,%5,%6,%7}, {%8,%9}, {%0,%1,%2,%3};"
        : "+f"(c[0]), "+f"(c[1]), "+f"(c[2]), "+f"(c[3])
        : "r"(a[0]), "r"(a[1]), "r"(a[2]), "r"(a[3]), "r"(b0), "r"(b1));
}
__device__ __forceinline__ float ex2f(float x) { float y; asm("ex2.approx.f32 %0, %1;" : "=f"(y) : "f"(x)); return y; }

#define SW128(o) ((o) ^ (((o) >> 3) & 0x70))

// ---------------------------------------------------------------------------
// conv: fp32 -> fp16 via PACKED converts (cvt.rn.f16x2.f32): 4 instrs / 8 elems
// ---------------------------------------------------------------------------
__device__ __forceinline__ uint4 cvt8(const float4 v0, const float4 v1) {
    __half2 h[4];
    h[0] = __floats2half2_rn(v0.x, v0.y);
    h[1] = __floats2half2_rn(v0.z, v0.w);
    h[2] = __floats2half2_rn(v1.x, v1.y);
    h[3] = __floats2half2_rn(v1.z, v1.w);
    return *(uint4*)h;
}

__global__ __launch_bounds__(256) void conv_all(const float* __restrict__ x, WPtrs p) {
    const int blk = blockIdx.x;
    const int tid = threadIdx.x;
    if (blk < 256) {                      // ---- x path: 65536 chunks of 8
        const int chunk = blk * 256 + tid;
        const int m  = chunk >> 6;
        const int k8 = (chunk & 63) << 3;
        const float4 v0 = *(const float4*)&x[(size_t)m * DD + k8];
        const float4 v1 = *(const float4*)&x[(size_t)m * DD + k8 + 4];
        *(uint4*)&gA[(size_t)m * DD + k8] = cvt8(v0, v1);
    } else {                              // ---- W path: 196608 chunks
        const int t   = (blk - 256) * 256 + tid;
        const int w   = t >> 15;
        const int rem = t & 32767;
        const int o   = rem >> 6;
        const int k8  = (rem & 63) << 3;
        const float4 v0 = *(const float4*)&p.W[w][(size_t)o * DD + k8];
        const float4 v1 = *(const float4*)&p.W[w][(size_t)o * DD + k8 + 4];
        *(uint4*)&gB[((size_t)w * DD + o) * DD + k8] = cvt8(v0, v1);
    }
}

// ---------------------------------------------------------------------------
// mma.sync fp16 GEMM: D[1024,3072] = xh @ wh^T + bias  (K=512, 8 chunks)
// CTA tile 128x96, 3-stage cp.async pipeline, 256 CTAs = one wave. (unchanged)
// ---------------------------------------------------------------------------
__device__ __forceinline__ void load_chunk(int tid, int m0, int ng, int c, uint32_t stg) {
    const int kb = c * KC;
    const uint32_t sAb = stg, sBb = stg + 16384u;
    #pragma unroll
    for (int t = 0; t < 4; t++) {
        int idx = tid + t * 256;
        int row = idx >> 3, c16 = idx & 7;
        const char* ga = (const char*)gA + ((size_t)(m0 + row) * DD + kb) * 2 + c16 * 16;
        cp16(sAb + SW128(row * 128 + c16 * 16), ga);
    }
    #pragma unroll
    for (int t = 0; t < 3; t++) {
        int idx = tid + t * 256;
        int row = idx >> 3, c16 = idx & 7;
        const char* gb = (const char*)gB + ((size_t)(ng + row) * DD + kb) * 2 + c16 * 16;
        cp16(sBb + SW128(row * 128 + c16 * 16), gb);
    }
    cp_commit();
}

__global__ __launch_bounds__(256, 2) void gemm_mma(WPtrs p) {
    extern __shared__ __align__(1024) char dsm[];
    const uint32_t sbase = smem_u32(dsm);

    const int tid  = threadIdx.x;
    const int wid  = tid >> 5, lane = tid & 31;
    const int wm   = wid & 3;
    const int wn   = wid >> 2;
    const int m0 = blockIdx.x * MT;
    const int ng = blockIdx.y * NT;

    float acc[2][6][4];
    #pragma unroll
    for (int i = 0; i < 2; i++)
        #pragma unroll
        for (int j = 0; j < 6; j++)
            #pragma unroll
            for (int q = 0; q < 4; q++) acc[i][j][q] = 0.f;

    load_chunk(tid, m0, ng, 0, sbase);
    load_chunk(tid, m0, ng, 1, sbase + STG_BYTES);

    const int a_row  = wm * 32 + (lane & 15);
    const int a_koff = ((lane >> 4) << 3) * 2;
    const int b_row  = wn * 48 + (lane & 7) + ((lane >> 4) << 3);
    const int b_koff = (((lane >> 3) & 1) << 3) * 2;

    int slot = 0;
    int nslot = 2;
    for (int ch = 0; ch < NCH; ch++) {
        cp_wait1();
        __syncthreads();

        if (ch + 2 < NCH) load_chunk(tid, m0, ng, ch + 2, sbase + nslot * STG_BYTES);
        else cp_commit();

        const uint32_t sAb = sbase + slot * STG_BYTES;
        const uint32_t sBb = sAb + 16384u;
        #pragma unroll
        for (int ks = 0; ks < 4; ks++) {
            const int kb = ks * 32;
            uint32_t a[2][4];
            #pragma unroll
            for (int mt = 0; mt < 2; mt++)
                ldsm4(a[mt], sAb + SW128((a_row + mt * 16) * 128 + kb + a_koff));
            uint32_t b[3][4];
            #pragma unroll
            for (int nt = 0; nt < 3; nt++)
                ldsm4(b[nt], sBb + SW128((b_row + nt * 16) * 128 + kb + b_koff));
            #pragma unroll
            for (int mt = 0; mt < 2; mt++)
                #pragma unroll
                for (int nb = 0; nb < 6; nb++)
                    mma16816(acc[mt][nb], a[mt], b[nb >> 1][(nb & 1) * 2], b[nb >> 1][(nb & 1) * 2 + 1]);
        }
        nslot = slot;
        slot = (slot == 2) ? 0 : slot + 1;
    }

    const int qrow = lane >> 2;
    const int qcol = (lane & 3) * 2;
    #pragma unroll
    for (int mt = 0; mt < 2; mt++) {
        const int r0 = m0 + wm * 32 + mt * 16 + qrow;
        #pragma unroll
        for (int nb = 0; nb < 6; nb++) {
            const int n  = ng + wn * 48 + nb * 8 + qcol;
            const int nw = n >> 9;
            const int no = n & 511;
            const float2 b2 = *(const float2*)&p.b[nw][no];
            float* d0 = &g_proj[((size_t)nw * MM + r0) * DD + no];
            float* d1 = &g_proj[((size_t)nw * MM + r0 + 8) * DD + no];
            ((float2*)d0)[0] = {acc[mt][nb][0] + b2.x, acc[mt][nb][1] + b2.y};
            ((float2*)d1)[0] = {acc[mt][nb][2] + b2.x, acc[mt][nb][3] + b2.y};
        }
    }
}

// ---------------------------------------------------------------------------
// attn: bucketed-moment temporal softmax
// 256 threads/CTA (each owns features i and i+256), 8 warps == 8 buckets,
// each warp scans the full D for its bucket. ~5 CTAs/SM -> 1.4 waves.
// ---------------------------------------------------------------------------
__global__ __launch_bounds__(256) void attn_kernel(float* __restrict__ out) {
    const int m    = blockIdx.x;
    const int tid  = threadIdx.x;
    const int lane = tid & 31;
    const int wid  = tid >> 5;    // 8 warps
    const float LOG2E = 1.4426950408889634f;

    const float* __restrict__ Qf = g_proj + (size_t)0 * MM * DD + (size_t)m * DD;
    const float* __restrict__ Kf = g_proj + (size_t)1 * MM * DD + (size_t)m * DD;
    const float* __restrict__ Vf = g_proj + (size_t)2 * MM * DD + (size_t)m * DD;
    const float* __restrict__ Qt = g_proj + (size_t)3 * MM * DD + (size_t)m * DD;
    const float* __restrict__ Kt = g_proj + (size_t)4 * MM * DD + (size_t)m * DD;
    const float* __restrict__ Vt = g_proj + (size_t)5 * MM * DD + (size_t)m * DD;

    __shared__ __align__(16) float sK[DD];
    __shared__ __align__(16) float sV[DD];
    __shared__ float sMA[NB][8];
    __shared__ float sMM[NB][8];
    __shared__ float redA[8], redB[8], redC[8];

    const int i0 = tid, i1 = tid + 256;
    const float kt0 = Kt[i0], kt1 = Kt[i1];
    sK[i0] = kt0; sK[i1] = kt1;
    sV[i0] = Vt[i0]; sV[i1] = Vt[i1];
    const float s0  = Qf[i0] * Kf[i0];
    const float s1  = Qf[i1] * Kf[i1];
    const float vf0 = Vf[i0], vf1 = Vf[i1];
    const float c0v = Qt[i0], c1v = Qt[i1];

    float smax = fmaxf(s0, s1), cmin = fminf(c0v, c1v), cmax = fmaxf(c0v, c1v);
    #pragma unroll
    for (int off = 16; off; off >>= 1) {
        smax = fmaxf(smax, __shfl_xor_sync(0xffffffffu, smax, off));
        cmin = fminf(cmin, __shfl_xor_sync(0xffffffffu, cmin, off));
        cmax = fmaxf(cmax, __shfl_xor_sync(0xffffffffu, cmax, off));
    }
    if (lane == 0) { redA[wid] = smax; redB[wid] = cmin; redC[wid] = cmax; }
    __syncthreads();   // also publishes sK / sV
    smax = redA[0]; cmin = redB[0]; cmax = redC[0];
    #pragma unroll
    for (int t = 1; t < 8; t++) {
        smax = fmaxf(smax, redA[t]);
        cmin = fminf(cmin, redB[t]);
        cmax = fmaxf(cmax, redC[t]);
    }
    __syncthreads();   // protect redA before reuse

    // feature branch (both items)
    const float e0 = ex2f((s0 - smax) * LOG2E);
    const float e1 = ex2f((s1 - smax) * LOG2E);
    float zf = e0 + e1;
    #pragma unroll
    for (int off = 16; off; off >>= 1)
        zf += __shfl_xor_sync(0xffffffffu, zf, off);
    if (lane == 0) redA[wid] = zf;
    __syncthreads();
    zf = redA[0];
    #pragma unroll
    for (int t = 1; t < 8; t++) zf += redA[t];
    const float ctx_f0 = (e0 / zf) * vf0;
    const float ctx_f1 = (e1 / zf) * vf1;

    // ---- temporal phase 1: warp wid == bucket wid scans the full D ----
    const float bw = (cmax - cmin) * (1.0f / NB);
    const float c0 = fmaf((float)wid + 0.5f, bw, cmin);
    const float c0l = c0 * LOG2E;

    float a1[ND], m1[ND], a2[ND], m2[ND];
    #pragma unroll
    for (int n = 0; n < ND; n++) { a1[n] = 0.f; m1[n] = 0.f; a2[n] = 0.f; m2[n] = 0.f; }

    #pragma unroll
    for (int jj = 0; jj < DD / 64; jj++) {
        const int j = jj * 64 + lane;
        const float ka = sK[j],      va = sV[j];
        const float kb = sK[j + 32], vb = sV[j + 32];
        float pa = ex2f(c0l * ka);
        float pb = ex2f(c0l * kb);
        #pragma unroll
        for (int n = 0; n < ND; n++) {
            a1[n] += pa;
            a2[n] += pb;
            m1[n]  = fmaf(pa, va, m1[n]);
            m2[n]  = fmaf(pb, vb, m2[n]);
            if (n < ND - 1) { pa *= ka; pb *= kb; }
        }
    }
    #pragma unroll
    for (int n = 0; n < ND; n++) {
        float av = a1[n] + a2[n], mv = m1[n] + m2[n];
        #pragma unroll
        for (int off = 16; off; off >>= 1) {
            av += __shfl_xor_sync(0xffffffffu, av, off);
            mv += __shfl_xor_sync(0xffffffffu, mv, off);
        }
        if (lane == 0) { sMA[wid][n] = av; sMM[wid][n] = mv; }
    }
    __syncthreads();

    // ---- temporal phase 2: per-item Horner in d = c - c0_b ----
    const float W  = cmax - cmin;
    const float sc = (W > 0.f) ? ((float)NB / W) : 0.f;
    const float IF[ND] = {1.f, 1.f, 0.5f, 1.f/6.f, 1.f/24.f, 1.f/120.f};

    #pragma unroll
    for (int item = 0; item < 2; item++) {
        const float c = item ? c1v : c0v;
        int b = (int)((c - cmin) * sc);
        b = (b > NB - 1) ? NB - 1 : ((b < 0) ? 0 : b);
        const float d = c - fmaf((float)b + 0.5f, bw, cmin);
        const float* MA  = sMA[b];
        const float* MMp = sMM[b];
        float den = MA[ND - 1] * IF[ND - 1];
        float num = MMp[ND - 1] * IF[ND - 1];
        #pragma unroll
        for (int n = ND - 2; n >= 0; n--) {
            den = fmaf(den, d, MA[n] * IF[n]);
            num = fmaf(num, d, MMp[n] * IF[n]);
        }
        const float ctx_f = item ? ctx_f1 : ctx_f0;
        out[(size_t)m * DD + (item ? i1 : i0)] = ctx_f + num / den;
    }
}

extern "C" void kernel_launch(void* const* d_in, const int* in_sizes, int n_in,
                              void* d_out, int out_size) {
    (void)in_sizes; (void)n_in; (void)out_size;
    const float* x = (const float*)d_in[0];
    WPtrs p;
    for (int w = 0; w < NWT; w++) {
        p.W[w] = (const float*)d_in[1 + 2 * w];
        p.b[w] = (const float*)d_in[2 + 2 * w];
    }
    cudaFuncSetAttribute(gemm_mma, cudaFuncAttributeMaxDynamicSharedMemorySize, GSMEM);
    conv_all<<<1024, 256>>>(x, p);
    gemm_mma<<<dim3(MM / MT, NN / NT), 256, GSMEM>>>(p);
    attn_kernel<<<MM, 256>>>((float*)d_out);
}

// round 12
// speedup vs baseline: 4.1296x; 1.0366x over previous
#include <cuda_runtime.h>
#include <cuda_fp16.h>
#include <cstdint>

#define BB 8
#define TT 128
#define DD 512
#define MM (BB*TT)          // 1024 tokens
#define NWT 6
#define NN (NWT*DD)         // 3072 total output cols
#define KC 64
#define NCH (DD/KC)         // 8 chunks (pure fp16, K=512)
#define MT 128
#define NT 96               // 8x32 = 256 CTAs -> one full wave at 2 CTAs/SM
#define NSTG 3
#define STG_BYTES (16384+12288)   // A 16KB + B 12KB per stage
#define GSMEM (NSTG*STG_BYTES)
#define NB 8                // temporal buckets == warps per CTA (attn)
#define ND 6                // Taylor terms (degree 5)

__device__ float g_proj[NWT * MM * DD];
__device__ __half gA[(size_t)MM * DD];           // 1 MB  xh

struct WPtrs { const float* W[NWT]; const float* b[NWT]; };

// ---------------------------------------------------------------------------
__device__ __forceinline__ uint32_t smem_u32(const void* p) {
    uint32_t a;
    asm("{ .reg .u64 t; cvta.to.shared.u64 t, %1; cvt.u32.u64 %0, t; }" : "=r"(a) : "l"(p));
    return a;
}
__device__ __forceinline__ void cp16(uint32_t saddr, const void* g) {
    asm volatile("cp.async.cg.shared.global [%0], [%1], 16;" :: "r"(saddr), "l"(g));
}
__device__ __forceinline__ void cp_commit() { asm volatile("cp.async.commit_group;" ::: "memory"); }
__device__ __forceinline__ void cp_wait1()  { asm volatile("cp.async.wait_group 1;" ::: "memory"); }
__device__ __forceinline__ void ldsm4(uint32_t* d, uint32_t a) {
    asm volatile("ldmatrix.sync.aligned.m8n8.x4.shared.b16 {%0,%1,%2,%3}, [%4];"
        : "=r"(d[0]), "=r"(d[1]), "=r"(d[2]), "=r"(d[3]) : "r"(a));
}
__device__ __forceinline__ void mma16816(float* c, const uint32_t* a, uint32_t b0, uint32_t b1) {
    asm volatile(
        "mma.sync.aligned.m16n8k16.row.col.f32.f16.f16.f32 "
        "{%0,%1,%2,%3}, {%4,%5,%6,%7}, {%8,%9}, {%0,%1,%2,%3};"
        : "+f"(c[0]), "+f"(c[1]), "+f"(c[2]), "+f"(c[3])
        : "r"(a[0]), "r"(a[1]), "r"(a[2]), "r"(a[3]), "r"(b0), "r"(b1));
}
__device__ __forceinline__ float ex2f(float x) { float y; asm("ex2.approx.f32 %0, %1;" : "=f"(y) : "f"(x)); return y; }

#define SW128(o) ((o) ^ (((o) >> 3) & 0x70))

__device__ __forceinline__ uint4 cvt8(const float4 v0, const float4 v1) {
    __half2 h[4];
    h[0] = __floats2half2_rn(v0.x, v0.y);
    h[1] = __floats2half2_rn(v0.z, v0.w);
    h[2] = __floats2half2_rn(v1.x, v1.y);
    h[3] = __floats2half2_rn(v1.z, v1.w);
    return *(uint4*)h;
}

// ---------------------------------------------------------------------------
// conv: x only -> fp16 (W conversion is fused into the GEMM)
// ---------------------------------------------------------------------------
__global__ __launch_bounds__(256) void conv_x(const float* __restrict__ x) {
    const int chunk = blockIdx.x * 256 + threadIdx.x;   // 65536 chunks of 8
    const int m  = chunk >> 6;
    const int k8 = (chunk & 63) << 3;
    const float4 v0 = *(const float4*)&x[(size_t)m * DD + k8];
    const float4 v1 = *(const float4*)&x[(size_t)m * DD + k8 + 4];
    *(uint4*)&gA[(size_t)m * DD + k8] = cvt8(v0, v1);
}

// ---------------------------------------------------------------------------
// mma.sync fp16 GEMM with fused W conversion:
//   A (xh fp16) via cp.async 2-ahead;  B (W fp32) via LDG->cvt->STS 1-ahead.
// CTA tile 128x96, 3-slot smem ring, 256 CTAs = one wave.
// ---------------------------------------------------------------------------
__device__ __forceinline__ void cpA(int tid, int m0, int c, uint32_t stg) {
    const int kb = c * KC;
    #pragma unroll
    for (int t = 0; t < 4; t++) {
        int idx = tid + t * 256;
        int row = idx >> 3, c16 = idx & 7;
        const char* ga = (const char*)gA + ((size_t)(m0 + row) * DD + kb) * 2 + c16 * 16;
        cp16(stg + SW128(row * 128 + c16 * 16), ga);
    }
    cp_commit();
}

__global__ __launch_bounds__(256, 2) void gemm_mma(WPtrs p) {
    extern __shared__ __align__(1024) char dsm[];
    const uint32_t sbase = smem_u32(dsm);

    const int tid  = threadIdx.x;
    const int wid  = tid >> 5, lane = tid & 31;
    const int wm   = wid & 3;        // m offset = wm*32
    const int wn   = wid >> 2;       // n offset = wn*48
    const int m0 = blockIdx.x * MT;
    const int ng = blockIdx.y * NT;

    // per-thread W source pointers for the 3 B-groups (row/col fixed, k varies)
    const float* bsrc[3];
    int brow[3], bc8[3];
    #pragma unroll
    for (int j = 0; j < 3; j++) {
        int g = tid + j * 256;            // 768 groups: 96 rows x 8 col-groups
        brow[j] = g >> 3;
        bc8[j]  = g & 7;
        int n = ng + brow[j];
        bsrc[j] = p.W[n >> 9] + (size_t)(n & 511) * DD + bc8[j] * 8;
    }

    float acc[2][6][4];
    #pragma unroll
    for (int i = 0; i < 2; i++)
        #pragma unroll
        for (int j = 0; j < 6; j++)
            #pragma unroll
            for (int q = 0; q < 4; q++) acc[i][j][q] = 0.f;

    float4 bv[6];                         // B chunk in flight (fp32)

    // ---- prologue: B0 regs, A0/A1 cp.async, STS B0, B1 regs ----
    #pragma unroll
    for (int j = 0; j < 3; j++) {
        bv[2*j]   = *(const float4*)(bsrc[j]);
        bv[2*j+1] = *(const float4*)(bsrc[j] + 4);
    }
    cpA(tid, m0, 0, sbase);
    cpA(tid, m0, 1, sbase + STG_BYTES);
    #pragma unroll
    for (int j = 0; j < 3; j++)
        *(uint4*)(dsm + 16384 + SW128(brow[j] * 128 + bc8[j] * 16)) = cvt8(bv[2*j], bv[2*j+1]);
    #pragma unroll
    for (int j = 0; j < 3; j++) {
        bv[2*j]   = *(const float4*)(bsrc[j] + KC);
        bv[2*j+1] = *(const float4*)(bsrc[j] + KC + 4);
    }
    cp_wait1();           // A0 resident
    __syncthreads();      // B0 visible

    const int a_row  = wm * 32 + (lane & 15);
    const int a_koff = ((lane >> 4) << 3) * 2;
    const int b_row  = wn * 48 + (lane & 7) + ((lane >> 4) << 3);
    const int b_koff = (((lane >> 3) & 1) << 3) * 2;

    int slot = 0;
    for (int ch = 0; ch < NCH; ch++) {
        // issue A (ch+2)
        if (ch + 2 < NCH) cpA(tid, m0, ch + 2, sbase + ((ch + 2) % 3) * STG_BYTES);
        else cp_commit();

        // compute chunk ch from slot
        const uint32_t sAb = sbase + slot * STG_BYTES;
        const uint32_t sBb = sAb + 16384u;
        #pragma unroll
        for (int ks = 0; ks < 4; ks++) {
            const int kb = ks * 32;
            uint32_t a[2][4];
            #pragma unroll
            for (int mt = 0; mt < 2; mt++)
                ldsm4(a[mt], sAb + SW128((a_row + mt * 16) * 128 + kb + a_koff));
            uint32_t b[3][4];
            #pragma unroll
            for (int nt = 0; nt < 3; nt++)
                ldsm4(b[nt], sBb + SW128((b_row + nt * 16) * 128 + kb + b_koff));
            #pragma unroll
            for (int mt = 0; mt < 2; mt++)
                #pragma unroll
                for (int nb = 0; nb < 6; nb++)
                    mma16816(acc[mt][nb], a[mt], b[nb >> 1][(nb & 1) * 2], b[nb >> 1][(nb & 1) * 2 + 1]);
        }

        // convert+STS B(ch+1) into slot (ch+1)%3; then load B(ch+2) regs
        if (ch + 1 < NCH) {
            char* bdst = dsm + ((ch + 1) % 3) * STG_BYTES + 16384;
            #pragma unroll
            for (int j = 0; j < 3; j++)
                *(uint4*)(bdst + SW128(brow[j] * 128 + bc8[j] * 16)) = cvt8(bv[2*j], bv[2*j+1]);
            if (ch + 2 < NCH) {
                const int k = (ch + 2) * KC;
                #pragma unroll
                for (int j = 0; j < 3; j++) {
                    bv[2*j]   = *(const float4*)(bsrc[j] + k);
                    bv[2*j+1] = *(const float4*)(bsrc[j] + k + 4);
                }
            }
        }

        cp_wait1();       // A(ch+1) resident
        __syncthreads();  // B(ch+1) visible; slot rotation safe
        slot = (slot == 2) ? 0 : slot + 1;
    }

    // epilogue: + bias, write fp32 projections (tile may span W matrices)
    const int qrow = lane >> 2;
    const int qcol = (lane & 3) * 2;
    #pragma unroll
    for (int mt = 0; mt < 2; mt++) {
        const int r0 = m0 + wm * 32 + mt * 16 + qrow;
        #pragma unroll
        for (int nb = 0; nb < 6; nb++) {
            const int n  = ng + wn * 48 + nb * 8 + qcol;
            const int nw = n >> 9;
            const int no = n & 511;
            const float2 b2 = *(const float2*)&p.b[nw][no];
            float* d0 = &g_proj[((size_t)nw * MM + r0) * DD + no];
            float* d1 = &g_proj[((size_t)nw * MM + r0 + 8) * DD + no];
            ((float2*)d0)[0] = {acc[mt][nb][0] + b2.x, acc[mt][nb][1] + b2.y};
            ((float2*)d1)[0] = {acc[mt][nb][2] + b2.x, acc[mt][nb][3] + b2.y};
        }
    }
}

// ---------------------------------------------------------------------------
// attn: bucketed-moment temporal softmax (unchanged from R11)
// ---------------------------------------------------------------------------
__global__ __launch_bounds__(256) void attn_kernel(float* __restrict__ out) {
    const int m    = blockIdx.x;
    const int tid  = threadIdx.x;
    const int lane = tid & 31;
    const int wid  = tid >> 5;    // 8 warps
    const float LOG2E = 1.4426950408889634f;

    const float* __restrict__ Qf = g_proj + (size_t)0 * MM * DD + (size_t)m * DD;
    const float* __restrict__ Kf = g_proj + (size_t)1 * MM * DD + (size_t)m * DD;
    const float* __restrict__ Vf = g_proj + (size_t)2 * MM * DD + (size_t)m * DD;
    const float* __restrict__ Qt = g_proj + (size_t)3 * MM * DD + (size_t)m * DD;
    const float* __restrict__ Kt = g_proj + (size_t)4 * MM * DD + (size_t)m * DD;
    const float* __restrict__ Vt = g_proj + (size_t)5 * MM * DD + (size_t)m * DD;

    __shared__ __align__(16) float sK[DD];
    __shared__ __align__(16) float sV[DD];
    __shared__ float sMA[NB][8];
    __shared__ float sMM[NB][8];
    __shared__ float redA[8], redB[8], redC[8];

    const int i0 = tid, i1 = tid + 256;
    sK[i0] = Kt[i0]; sK[i1] = Kt[i1];
    sV[i0] = Vt[i0]; sV[i1] = Vt[i1];
    const float s0  = Qf[i0] * Kf[i0];
    const float s1  = Qf[i1] * Kf[i1];
    const float vf0 = Vf[i0], vf1 = Vf[i1];
    const float c0v = Qt[i0], c1v = Qt[i1];

    float smax = fmaxf(s0, s1), cmin = fminf(c0v, c1v), cmax = fmaxf(c0v, c1v);
    #pragma unroll
    for (int off = 16; off; off >>= 1) {
        smax = fmaxf(smax, __shfl_xor_sync(0xffffffffu, smax, off));
        cmin = fminf(cmin, __shfl_xor_sync(0xffffffffu, cmin, off));
        cmax = fmaxf(cmax, __shfl_xor_sync(0xffffffffu, cmax, off));
    }
    if (lane == 0) { redA[wid] = smax; redB[wid] = cmin; redC[wid] = cmax; }
    __syncthreads();
    smax = redA[0]; cmin = redB[0]; cmax = redC[0];
    #pragma unroll
    for (int t = 1; t < 8; t++) {
        smax = fmaxf(smax, redA[t]);
        cmin = fminf(cmin, redB[t]);
        cmax = fmaxf(cmax, redC[t]);
    }
    __syncthreads();

    const float e0 = ex2f((s0 - smax) * LOG2E);
    const float e1 = ex2f((s1 - smax) * LOG2E);
    float zf = e0 + e1;
    #pragma unroll
    for (int off = 16; off; off >>= 1)
        zf += __shfl_xor_sync(0xffffffffu, zf, off);
    if (lane == 0) redA[wid] = zf;
    __syncthreads();
    zf = redA[0];
    #pragma unroll
    for (int t = 1; t < 8; t++) zf += redA[t];
    const float ctx_f0 = (e0 / zf) * vf0;
    const float ctx_f1 = (e1 / zf) * vf1;

    const float bw = (cmax - cmin) * (1.0f / NB);
    const float c0 = fmaf((float)wid + 0.5f, bw, cmin);
    const float c0l = c0 * LOG2E;

    float a1[ND], m1[ND], a2[ND], m2[ND];
    #pragma unroll
    for (int n = 0; n < ND; n++) { a1[n] = 0.f; m1[n] = 0.f; a2[n] = 0.f; m2[n] = 0.f; }

    #pragma unroll
    for (int jj = 0; jj < DD / 64; jj++) {
        const int j = jj * 64 + lane;
        const float ka = sK[j],      va = sV[j];
        const float kb = sK[j + 32], vb = sV[j + 32];
        float pa = ex2f(c0l * ka);
        float pb = ex2f(c0l * kb);
        #pragma unroll
        for (int n = 0; n < ND; n++) {
            a1[n] += pa;
            a2[n] += pb;
            m1[n]  = fmaf(pa, va, m1[n]);
            m2[n]  = fmaf(pb, vb, m2[n]);
            if (n < ND - 1) { pa *= ka; pb *= kb; }
        }
    }
    #pragma unroll
    for (int n = 0; n < ND; n++) {
        float av = a1[n] + a2[n], mv = m1[n] + m2[n];
        #pragma unroll
        for (int off = 16; off; off >>= 1) {
            av += __shfl_xor_sync(0xffffffffu, av, off);
            mv += __shfl_xor_sync(0xffffffffu, mv, off);
        }
        if (lane == 0) { sMA[wid][n] = av; sMM[wid][n] = mv; }
    }
    __syncthreads();

    const float W  = cmax - cmin;
    const float sc = (W > 0.f) ? ((float)NB / W) : 0.f;
    const float IF[ND] = {1.f, 1.f, 0.5f, 1.f/6.f, 1.f/24.f, 1.f/120.f};

    #pragma unroll
    for (int item = 0; item < 2; item++) {
        const float c = item ? c1v : c0v;
        int b = (int)((c - cmin) * sc);
        b = (b > NB - 1) ? NB - 1 : ((b < 0) ? 0 : b);
        const float d = c - fmaf((float)b + 0.5f, bw, cmin);
        const float* MA  = sMA[b];
        const float* MMp = sMM[b];
        float den = MA[ND - 1] * IF[ND - 1];
        float num = MMp[ND - 1] * IF[ND - 1];
        #pragma unroll
        for (int n = ND - 2; n >= 0; n--) {
            den = fmaf(den, d, MA[n] * IF[n]);
            num = fmaf(num, d, MMp[n] * IF[n]);
        }
        const float ctx_f = item ? ctx_f1 : ctx_f0;
        out[(size_t)m * DD + (item ? i1 : i0)] = ctx_f + num / den;
    }
}

extern "C" void kernel_launch(void* const* d_in, const int* in_sizes, int n_in,
                              void* d_out, int out_size) {
    (void)in_sizes; (void)n_in; (void)out_size;
    const float* x = (const float*)d_in[0];
    WPtrs p;
    for (int w = 0; w < NWT; w++) {
        p.W[w] = (const float*)d_in[1 + 2 * w];
        p.b[w] = (const float*)d_in[2 + 2 * w];
    }
    cudaFuncSetAttribute(gemm_mma, cudaFuncAttributeMaxDynamicSharedMemorySize, GSMEM);
    conv_x<<<256, 256>>>(x);
    gemm_mma<<<dim3(MM / MT, NN / NT), 256, GSMEM>>>(p);
    attn_kernel<<<MM, 256>>>((float*)d_out);
}